// round 5
// baseline (speedup 1.0000x reference)
#include <cuda_runtime.h>
#include <cuda_bf16.h>
#include <stdint.h>
#include <math.h>

// ---------------------------------------------------------------------------
// Problem constants: b=4, c=128, a=25, h=w=32
// ---------------------------------------------------------------------------
#define TOK_M   102400
#define D_MOD   256
#define D_FF    512
#define QKV_N   768
#define BA      100
#define PIX     1024
#define CCH     128
#define AA      25
#define KIN     1152        // c*9

// ------------------------- scratch (static device) -------------------------
__device__ float g_T  [TOK_M * D_MOD];
__device__ float g_PE [TOK_M * D_MOD];
__device__ float g_QKV[TOK_M * QKV_N];
__device__ float g_AO [TOK_M * D_MOD];
__device__ float g_S2 [TOK_M * D_MOD];
__device__ float g_XF [TOK_M * D_MOD];

__device__ __nv_bfloat16 gA_hi[(size_t)TOK_M * KIN];
__device__ __nv_bfloat16 gA_lo[(size_t)TOK_M * KIN];
__device__ __nv_bfloat16 gX_hi[TOK_M * D_MOD],  gX_lo[TOK_M * D_MOD];
__device__ __nv_bfloat16 gAO_hi[TOK_M * D_MOD], gAO_lo[TOK_M * D_MOD];
__device__ __nv_bfloat16 gY_hi[TOK_M * D_MOD],  gY_lo[TOK_M * D_MOD];
__device__ __nv_bfloat16 gF_hi[TOK_M * D_FF],   gF_lo[TOK_M * D_FF];

__device__ __nv_bfloat16 gWmlp_hi [D_MOD * KIN],   gWmlp_lo [D_MOD * KIN];
__device__ __nv_bfloat16 gWqkv_hi [QKV_N * D_MOD], gWqkv_lo [QKV_N * D_MOD];
__device__ __nv_bfloat16 gWproj_hi[D_MOD * D_MOD], gWproj_lo[D_MOD * D_MOD];
__device__ __nv_bfloat16 gW1_hi   [D_FF * D_MOD],  gW1_lo   [D_FF * D_MOD];
__device__ __nv_bfloat16 gW2_hi   [D_MOD * D_FF],  gW2_lo   [D_MOD * D_FF];

// ---------------------------------------------------------------------------
// base-target-legal PTX helpers (sm_80+): mma.sync, ldmatrix, cp.async
// ---------------------------------------------------------------------------
__device__ __forceinline__ uint32_t smem_u32(const void* p) {
    uint32_t a;
    asm("{ .reg .u64 t; cvta.to.shared.u64 t, %1; cvt.u32.u64 %0, t; }"
        : "=r"(a) : "l"(p));
    return a;
}
__device__ __forceinline__ void ldsm_x4(uint32_t* r, uint32_t addr) {
    asm volatile("ldmatrix.sync.aligned.m8n8.x4.shared.b16 {%0,%1,%2,%3}, [%4];"
        : "=r"(r[0]), "=r"(r[1]), "=r"(r[2]), "=r"(r[3]) : "r"(addr));
}
__device__ __forceinline__ void ldsm_x2(uint32_t* r, uint32_t addr) {
    asm volatile("ldmatrix.sync.aligned.m8n8.x2.shared.b16 {%0,%1}, [%2];"
        : "=r"(r[0]), "=r"(r[1]) : "r"(addr));
}
__device__ __forceinline__ void mma16816(float* c, const uint32_t* a, const uint32_t* b) {
    asm volatile(
        "mma.sync.aligned.m16n8k16.row.col.f32.bf16.bf16.f32 "
        "{%0,%1,%2,%3}, {%4,%5,%6,%7}, {%8,%9}, {%0,%1,%2,%3};"
        : "+f"(c[0]), "+f"(c[1]), "+f"(c[2]), "+f"(c[3])
        : "r"(a[0]), "r"(a[1]), "r"(a[2]), "r"(a[3]), "r"(b[0]), "r"(b[1]));
}
#define CP16(dst, src) \
    asm volatile("cp.async.cg.shared.global [%0], [%1], 16;" \
        :: "r"(dst), "l"(src) : "memory")
#define CP_COMMIT() asm volatile("cp.async.commit_group;" ::: "memory")
#define CP_WAIT0()  asm volatile("cp.async.wait_group 0;" ::: "memory")
#define CP_WAIT1()  asm volatile("cp.async.wait_group 1;" ::: "memory")

// ---------------------------------------------------------------------------
// bf16x3 HMMA GEMM: C[M,N] = Ahi@Bt_hi^T + Ahi@Bt_lo^T + Alo@Bt_hi^T
//   A [M,K] bf16 (hi/lo), Bt [N,K] bf16 (hi/lo).
// Tile BM=128, BN=64, BK=32; 256 threads = 8 warps (4 m x 2 n), warp 32x32.
// smem rows padded to 40 bf16 (80B) -> conflict-free ldmatrix.
// Epilogue: +bias, relu, +resid, write fp32 C and/or bf16 hi/lo.
// ---------------------------------------------------------------------------
#define RS 40                     // smem row stride in bf16
#define SM_AH 0                   // 128*40*2 = 10240 B
#define SM_AL 10240
#define SM_BH 20480               // 64*40*2 = 5120 B
#define SM_BL 25600
#define SM_BUF 30720              // per-stage bytes
#define GSM_TOTAL (2 * SM_BUF)    // 61440

__global__ __launch_bounds__(256) void gemm_mma(
    const __nv_bfloat16* __restrict__ Ahi, const __nv_bfloat16* __restrict__ Alo,
    const __nv_bfloat16* __restrict__ Bhi, const __nv_bfloat16* __restrict__ Blo,
    float* __restrict__ C, int M, int N, int K,
    const float* __restrict__ bias, const float* __restrict__ resid, int relu,
    __nv_bfloat16* __restrict__ Ohi, __nv_bfloat16* __restrict__ Olo)
{
    extern __shared__ char sm[];
    const uint32_t smb = smem_u32(sm);
    const int tid = threadIdx.x;
    const int lane = tid & 31;
    const int wid = tid >> 5;
    const int warpm = wid & 3;          // 0..3
    const int warpn = wid >> 2;         // 0..1
    const int m0 = blockIdx.y * 128;
    const int n0 = blockIdx.x * 64;

    // ---- loader geometry ----
    const int arow = tid >> 1;          // 0..127
    const int aseg = tid & 1;           // k halves (16 bf16 = 32B each)
    const uint32_t a_sm_off = (uint32_t)arow * (RS * 2) + aseg * 32;
    const __nv_bfloat16* pAh = Ahi + (size_t)(m0 + arow) * K + aseg * 16;
    const __nv_bfloat16* pAl = Alo + (size_t)(m0 + arow) * K + aseg * 16;

    const int bt   = tid & 127;
    const int brow = bt >> 1;           // 0..63
    const int bseg = bt & 1;
    const uint32_t b_sm_off = (uint32_t)brow * (RS * 2) + bseg * 32;
    const int is_blo = (tid >= 128);
    const __nv_bfloat16* pB =
        (is_blo ? Blo : Bhi) + (size_t)(n0 + brow) * K + bseg * 16;
    const uint32_t b_sm_base = is_blo ? SM_BL : SM_BH;

    const int nch = K >> 5;

    // prologue: chunk 0 -> stage 0
    {
        CP16(smb + SM_AH + a_sm_off,      pAh);
        CP16(smb + SM_AH + a_sm_off + 16, pAh + 8);
        CP16(smb + SM_AL + a_sm_off,      pAl);
        CP16(smb + SM_AL + a_sm_off + 16, pAl + 8);
        CP16(smb + b_sm_base + b_sm_off,      pB);
        CP16(smb + b_sm_base + b_sm_off + 16, pB + 8);
        CP_COMMIT();
    }

    float acc[2][4][4];
#pragma unroll
    for (int im = 0; im < 2; im++)
#pragma unroll
        for (int in = 0; in < 4; in++)
#pragma unroll
            for (int r = 0; r < 4; r++) acc[im][in][r] = 0.f;

    // ldmatrix per-lane address pieces (bf16 units within a tile)
    const uint32_t a_ld_row = (uint32_t)(warpm * 32 + (lane & 15));
    const uint32_t a_ld_k8  = (uint32_t)((lane >> 4) * 8);
    const int l15 = lane & 15;
    const uint32_t b_ld_row = (uint32_t)(warpn * 32 + (l15 & 7));
    const uint32_t b_ld_k8  = (uint32_t)(((l15 >> 3) & 1) * 8);

    for (int t = 0; t < nch; t++) {
        const uint32_t cur = (uint32_t)(t & 1) * SM_BUF;
        if (t + 1 < nch) {
            const uint32_t alt = (uint32_t)((t + 1) & 1) * SM_BUF;
            const size_t kc = (size_t)(t + 1) * 32;
            CP16(smb + alt + SM_AH + a_sm_off,      pAh + kc);
            CP16(smb + alt + SM_AH + a_sm_off + 16, pAh + kc + 8);
            CP16(smb + alt + SM_AL + a_sm_off,      pAl + kc);
            CP16(smb + alt + SM_AL + a_sm_off + 16, pAl + kc + 8);
            CP16(smb + alt + b_sm_base + b_sm_off,      pB + kc);
            CP16(smb + alt + b_sm_base + b_sm_off + 16, pB + kc + 8);
            CP_COMMIT();
            CP_WAIT1();
        } else {
            CP_WAIT0();
        }
        __syncthreads();

#pragma unroll
        for (int ks = 0; ks < 2; ks++) {
            uint32_t ah[2][4], al[2][4], bh[4][2], bl[4][2];
#pragma unroll
            for (int im = 0; im < 2; im++) {
                const uint32_t ao = cur +
                    ((a_ld_row + im * 16) * RS + ks * 16 + a_ld_k8) * 2;
                ldsm_x4(ah[im], smb + SM_AH + ao);
                ldsm_x4(al[im], smb + SM_AL + ao);
            }
#pragma unroll
            for (int in = 0; in < 4; in++) {
                const uint32_t bo = cur +
                    ((b_ld_row + in * 8) * RS + ks * 16 + b_ld_k8) * 2;
                ldsm_x2(bh[in], smb + SM_BH + bo);
                ldsm_x2(bl[in], smb + SM_BL + bo);
            }
#pragma unroll
            for (int im = 0; im < 2; im++)
#pragma unroll
                for (int in = 0; in < 4; in++) {
                    mma16816(acc[im][in], ah[im], bh[in]);
                    mma16816(acc[im][in], ah[im], bl[in]);
                    mma16816(acc[im][in], al[im], bh[in]);
                }
        }
        __syncthreads();
    }

    // ---- epilogue ----
#pragma unroll
    for (int im = 0; im < 2; im++) {
#pragma unroll
        for (int in = 0; in < 4; in++) {
            const int mrow = m0 + warpm * 32 + im * 16 + (lane >> 2);
            const int ncol = n0 + warpn * 32 + in * 8 + (lane & 3) * 2;
#pragma unroll
            for (int r = 0; r < 2; r++) {
                const int m = mrow + r * 8;
                float v0 = acc[im][in][r * 2 + 0];
                float v1 = acc[im][in][r * 2 + 1];
                if (bias)  { v0 += bias[ncol]; v1 += bias[ncol + 1]; }
                if (relu)  { v0 = fmaxf(v0, 0.f); v1 = fmaxf(v1, 0.f); }
                if (resid) {
                    const float* rp = resid + (size_t)m * N + ncol;
                    v0 += rp[0]; v1 += rp[1];
                }
                if (C) {
                    float2 f2; f2.x = v0; f2.y = v1;
                    *(float2*)(C + (size_t)m * N + ncol) = f2;
                }
                if (Ohi) {
                    __nv_bfloat16 h0 = __float2bfloat16_rn(v0);
                    __nv_bfloat16 h1 = __float2bfloat16_rn(v1);
                    __nv_bfloat162 hv; hv.x = h0; hv.y = h1;
                    __nv_bfloat162 lv;
                    lv.x = __float2bfloat16_rn(v0 - __bfloat162float(h0));
                    lv.y = __float2bfloat16_rn(v1 - __bfloat162float(h1));
                    *(__nv_bfloat162*)(Ohi + (size_t)m * N + ncol) = hv;
                    *(__nv_bfloat162*)(Olo + (size_t)m * N + ncol) = lv;
                }
            }
        }
    }
}

// ---------------------------------------------------------------------------
// weight transpose + split: W [K,N] fp32 -> Bt [N,K] bf16 hi/lo
// ---------------------------------------------------------------------------
__global__ void wsplit_kernel(const float* __restrict__ W, int K, int N,
                              __nv_bfloat16* __restrict__ oh,
                              __nv_bfloat16* __restrict__ ol)
{
    const int idx = blockIdx.x * 256 + threadIdx.x;
    if (idx >= K * N) return;
    const int k = idx / N, n = idx - k * N;
    const float v = W[idx];
    const __nv_bfloat16 h = __float2bfloat16_rn(v);
    oh[(size_t)n * K + k] = h;
    ol[(size_t)n * K + k] = __float2bfloat16_rn(v - __bfloat162float(h));
}

// ---------------------------------------------------------------------------
// elementwise split: X fp32 -> hi/lo bf16
// ---------------------------------------------------------------------------
__global__ void split_kernel(const float* __restrict__ X, size_t n,
                             __nv_bfloat16* __restrict__ oh,
                             __nv_bfloat16* __restrict__ ol)
{
    const size_t i = (size_t)blockIdx.x * 256 + threadIdx.x;
    if (i >= n) return;
    const float v = X[i];
    const __nv_bfloat16 h = __float2bfloat16_rn(v);
    oh[i] = h;
    ol[i] = __float2bfloat16_rn(v - __bfloat162float(h));
}

// ---------------------------------------------------------------------------
// im2col + split: src [b,c,a,h,w] -> A [m=p*100+ba][k=c*9+tap] bf16 hi/lo
// ---------------------------------------------------------------------------
__global__ void im2col_split(const float* __restrict__ src,
                             __nv_bfloat16* __restrict__ Ahi,
                             __nv_bfloat16* __restrict__ Alo)
{
    const size_t idx = (size_t)blockIdx.x * 256 + threadIdx.x;
    const int p = (int)(idx & 1023);
    const int rest = (int)(idx >> 10);
    const int c = rest & 127;
    const int ba = rest >> 7;
    const int b_ = ba / AA, a_ = ba - b_ * AA;
    const int i = p >> 5, j = p & 31;
    const float* xb = src + ((((size_t)(b_ * CCH + c)) * AA + a_) << 10);
    const size_t mrow = ((size_t)p * BA + ba) * KIN + c * 9;
    __nv_bfloat16* oh = Ahi + mrow;
    __nv_bfloat16* ol = Alo + mrow;
#pragma unroll
    for (int di = 0; di < 3; di++) {
        const int ii = i + di - 1;
#pragma unroll
        for (int dj = 0; dj < 3; dj++) {
            const int jj = j + dj - 1;
            float v = 0.f;
            if (ii >= 0 && ii < 32 && jj >= 0 && jj < 32) v = xb[ii * 32 + jj];
            const __nv_bfloat16 h = __float2bfloat16_rn(v);
            oh[di * 3 + dj] = h;
            ol[di * 3 + dj] = __float2bfloat16_rn(v - __bfloat162float(h));
        }
    }
}

// ---------------------------------------------------------------------------
// LayerNorm over D=256 -> bf16 hi/lo. Optional addsrc.
// ---------------------------------------------------------------------------
__global__ __launch_bounds__(256) void ln_kernel(
    const float* __restrict__ X, const float* __restrict__ addsrc,
    const float* __restrict__ g, const float* __restrict__ b,
    __nv_bfloat16* __restrict__ oh, __nv_bfloat16* __restrict__ ol)
{
    const size_t row = blockIdx.x;
    const int tid = threadIdx.x;
    __shared__ float red[8];

    float v = X[row * D_MOD + tid];
    if (addsrc) v += addsrc[row * D_MOD + tid];

    float s = v;
#pragma unroll
    for (int o = 16; o; o >>= 1) s += __shfl_xor_sync(0xffffffffu, s, o);
    if ((tid & 31) == 0) red[tid >> 5] = s;
    __syncthreads();
    float mean = 0.f;
#pragma unroll
    for (int i = 0; i < 8; i++) mean += red[i];
    mean *= (1.f / 256.f);
    __syncthreads();

    const float dev = v - mean;
    float q = dev * dev;
#pragma unroll
    for (int o = 16; o; o >>= 1) q += __shfl_xor_sync(0xffffffffu, q, o);
    if ((tid & 31) == 0) red[tid >> 5] = q;
    __syncthreads();
    float var = 0.f;
#pragma unroll
    for (int i = 0; i < 8; i++) var += red[i];
    var *= (1.f / 256.f);

    const float r = dev * rsqrtf(var + 1e-5f) * g[tid] + b[tid];
    const __nv_bfloat16 h = __float2bfloat16_rn(r);
    oh[row * D_MOD + tid] = h;
    ol[row * D_MOD + tid] = __float2bfloat16_rn(r - __bfloat162float(h));
}

// ---------------------------------------------------------------------------
// Fused attention (scalar): one CTA per pixel.
// ---------------------------------------------------------------------------
#define ATT_SMEM_FLOATS (25600 + 25600 + 256 + 800 + 800 + 64 + 64 + 8 + 8 + 8)
#define ATT_SMEM_BYTES  (ATT_SMEM_FLOATS * 4)

__global__ __launch_bounds__(256) void attn_kernel(
    const float* __restrict__ qkv, float* __restrict__ out,
    const float* __restrict__ Wl, const float* __restrict__ bl,
    const float* __restrict__ Ww, const float* __restrict__ bw,
    const float* __restrict__ lamb)
{
    extern __shared__ float smf[];
    float* Ks   = smf;
    float* Vs   = Ks + 25600;
    float* qs   = Vs + 25600;
    float* sraw = qs + 256;
    float* satt = sraw + 800;
    float* swl  = satt + 800;
    float* sww  = swl + 64;
    float* sbl  = sww + 64;
    float* sbw  = sbl + 8;
    float* slam = sbw + 8;

    const int tid = threadIdx.x;
    const int bq = blockIdx.x;
    const float scale = 0.17677669529663687f;

    if (tid < 64) { swl[tid] = Wl[tid]; sww[tid] = Ww[tid]; }
    if (tid < 8)  { sbl[tid] = bl[tid]; sbw[tid] = bw[tid]; slam[tid] = lamb[tid]; }

    const float* base = qkv + (size_t)bq * BA * QKV_N;
    for (int idx = tid; idx < 25600; idx += 256) {
        const int m = idx >> 8, cc = idx & 255;
        Ks[idx] = base[(size_t)m * QKV_N + 256 + cc];
        Vs[idx] = base[(size_t)m * QKV_N + 512 + cc];
    }
    __syncthreads();

    const int g = tid >> 5, lane = tid & 31;

    for (int n = 0; n < BA; n++) {
        qs[tid] = base[(size_t)n * QKV_N + tid] * scale;
        __syncthreads();

        for (int e = tid; e < 800; e += 256) {
            const int h = e / 100, m = e - h * 100;
            const float* kp = Ks + m * 256 + h * 32;
            const float* qp = qs + h * 32;
            float d = 0.f;
#pragma unroll
            for (int dd = 0; dd < 32; dd++) d += qp[dd] * kp[dd];
            sraw[e] = d;
        }
        __syncthreads();

        for (int e = tid; e < 800; e += 256) {
            const int gg = e / 100, m = e - gg * 100;
            float s = sbl[gg];
#pragma unroll
            for (int h = 0; h < 8; h++) s += sraw[h * 100 + m] * swl[gg * 8 + h];
            satt[e] = s;
        }
        __syncthreads();

        {
            float mx = -1e30f;
            for (int m = lane; m < 100; m += 32) mx = fmaxf(mx, satt[g * 100 + m]);
#pragma unroll
            for (int o = 16; o; o >>= 1) mx = fmaxf(mx, __shfl_xor_sync(0xffffffffu, mx, o));
            float sum = 0.f;
            for (int m = lane; m < 100; m += 32) {
                const float e2 = __expf(satt[g * 100 + m] - mx);
                sraw[g * 100 + m] = e2;
                sum += e2;
            }
#pragma unroll
            for (int o = 16; o; o >>= 1) sum += __shfl_xor_sync(0xffffffffu, sum, o);
            const float inv = 1.f / sum;
            for (int m = lane; m < 100; m += 32) sraw[g * 100 + m] *= inv;
        }
        __syncthreads();

        for (int e = tid; e < 800; e += 256) {
            const int gg = e / 100, m = e - gg * 100;
            float s = sbw[gg];
#pragma unroll
            for (int h = 0; h < 8; h++) s += sraw[h * 100 + m] * sww[gg * 8 + h];
            s = 0.01f + (s - 0.01f) * (1.f + slam[gg]);
            satt[e] = s;
        }
        __syncthreads();

        {
            const int d = lane;
            float o = 0.f;
            const float* vp = Vs + g * 32 + d;
            const float* ap = satt + g * 100;
#pragma unroll 4
            for (int m = 0; m < 100; m++) o += ap[m] * vp[m * 256];
            out[((size_t)bq * BA + n) * D_MOD + g * 32 + d] = o;
        }
        __syncthreads();
    }
}

// ---------------------------------------------------------------------------
// Token2SAI + 1x1x1 conv (scalar)
// ---------------------------------------------------------------------------
__global__ __launch_bounds__(256) void t2s_kernel(
    const float* __restrict__ F, const float* __restrict__ Wc,
    float* __restrict__ out)
{
    __shared__ float Wt[8 * 128];
    __shared__ float Fs[8 * 128];
    const int tid = threadIdx.x;
    const int p0 = blockIdx.x * 128;
    const int ba = blockIdx.y;
    const int b_ = ba / AA, a_ = ba - b_ * AA;
    const int tx = tid & 15;
    const int ty = tid >> 4;

    float acc[8][8];
#pragma unroll
    for (int i = 0; i < 8; i++)
#pragma unroll
        for (int j = 0; j < 8; j++) acc[i][j] = 0.f;

    const int wrow = tid >> 1, wcol = (tid & 1) * 4;

    for (int k0 = 0; k0 < D_MOD; k0 += 8) {
        float4 wv = *(const float4*)(Wc + (size_t)wrow * D_MOD + k0 + wcol);
        Wt[(wcol + 0) * 128 + wrow] = wv.x;
        Wt[(wcol + 1) * 128 + wrow] = wv.y;
        Wt[(wcol + 2) * 128 + wrow] = wv.z;
        Wt[(wcol + 3) * 128 + wrow] = wv.w;
        float4 fv = *(const float4*)(F + ((size_t)(p0 + wrow) * BA + ba) * D_MOD + k0 + wcol);
        Fs[(wcol + 0) * 128 + wrow] = fv.x;
        Fs[(wcol + 1) * 128 + wrow] = fv.y;
        Fs[(wcol + 2) * 128 + wrow] = fv.z;
        Fs[(wcol + 3) * 128 + wrow] = fv.w;
        __syncthreads();
#pragma unroll
        for (int kk = 0; kk < 8; kk++) {
            float a[8], b[8];
            *(float4*)(a)     = *(const float4*)&Wt[kk * 128 + ty * 8];
            *(float4*)(a + 4) = *(const float4*)&Wt[kk * 128 + ty * 8 + 4];
            *(float4*)(b)     = *(const float4*)&Fs[kk * 128 + tx * 8];
            *(float4*)(b + 4) = *(const float4*)&Fs[kk * 128 + tx * 8 + 4];
#pragma unroll
            for (int i = 0; i < 8; i++)
#pragma unroll
                for (int j = 0; j < 8; j++) acc[i][j] += a[i] * b[j];
        }
        __syncthreads();
    }

#pragma unroll
    for (int i = 0; i < 8; i++) {
        const int o = ty * 8 + i;
        float* op = out + ((size_t)(b_ * CCH + o) * AA + a_) * PIX + p0 + tx * 8;
        *(float4*)(op)     = *(float4*)(acc[i]);
        *(float4*)(op + 4) = *(float4*)(acc[i] + 4);
    }
}

// ---------------------------------------------------------------------------
extern "C" void kernel_launch(void* const* d_in, const int* in_sizes, int n_in,
                              void* d_out, int out_size)
{
    const float* buffer  = (const float*)d_in[0];
    const float* spa_pos = (const float*)d_in[1];
    const float* W_mlp   = (const float*)d_in[2];
    const float* g1      = (const float*)d_in[3];
    const float* b1      = (const float*)d_in[4];
    const float* Wqkv    = (const float*)d_in[5];
    const float* Wproj   = (const float*)d_in[6];
    const float* bproj   = (const float*)d_in[7];
    const float* Wl      = (const float*)d_in[8];
    const float* bl      = (const float*)d_in[9];
    const float* Ww      = (const float*)d_in[10];
    const float* bw      = (const float*)d_in[11];
    const float* lamb    = (const float*)d_in[12];
    const float* g2      = (const float*)d_in[13];
    const float* b2      = (const float*)d_in[14];
    const float* W1      = (const float*)d_in[15];
    const float* W2      = (const float*)d_in[16];
    const float* Wconv   = (const float*)d_in[17];
    float* out = (float*)d_out;

    float *T, *PE, *QKV, *AO, *S2, *XF;
    cudaGetSymbolAddress((void**)&T,   g_T);
    cudaGetSymbolAddress((void**)&PE,  g_PE);
    cudaGetSymbolAddress((void**)&QKV, g_QKV);
    cudaGetSymbolAddress((void**)&AO,  g_AO);
    cudaGetSymbolAddress((void**)&S2,  g_S2);
    cudaGetSymbolAddress((void**)&XF,  g_XF);

    __nv_bfloat16 *Ah, *Al, *Xh, *Xl, *AOh, *AOl, *Yh, *Yl, *Fh, *Fl;
    __nv_bfloat16 *Wmh, *Wml, *Wqh, *Wql, *Wph, *Wpl, *W1h, *W1l, *W2h, *W2l;
    cudaGetSymbolAddress((void**)&Ah,  gA_hi);   cudaGetSymbolAddress((void**)&Al,  gA_lo);
    cudaGetSymbolAddress((void**)&Xh,  gX_hi);   cudaGetSymbolAddress((void**)&Xl,  gX_lo);
    cudaGetSymbolAddress((void**)&AOh, gAO_hi);  cudaGetSymbolAddress((void**)&AOl, gAO_lo);
    cudaGetSymbolAddress((void**)&Yh,  gY_hi);   cudaGetSymbolAddress((void**)&Yl,  gY_lo);
    cudaGetSymbolAddress((void**)&Fh,  gF_hi);   cudaGetSymbolAddress((void**)&Fl,  gF_lo);
    cudaGetSymbolAddress((void**)&Wmh, gWmlp_hi);  cudaGetSymbolAddress((void**)&Wml, gWmlp_lo);
    cudaGetSymbolAddress((void**)&Wqh, gWqkv_hi);  cudaGetSymbolAddress((void**)&Wql, gWqkv_lo);
    cudaGetSymbolAddress((void**)&Wph, gWproj_hi); cudaGetSymbolAddress((void**)&Wpl, gWproj_lo);
    cudaGetSymbolAddress((void**)&W1h, gW1_hi);    cudaGetSymbolAddress((void**)&W1l, gW1_lo);
    cudaGetSymbolAddress((void**)&W2h, gW2_hi);    cudaGetSymbolAddress((void**)&W2l, gW2_lo);

    cudaFuncSetAttribute(attn_kernel, cudaFuncAttributeMaxDynamicSharedMemorySize,
                         ATT_SMEM_BYTES);
    cudaFuncSetAttribute(gemm_mma, cudaFuncAttributeMaxDynamicSharedMemorySize,
                         GSM_TOTAL);

    // 0) weight transpose + split
    wsplit_kernel<<<(KIN * D_MOD + 255) / 256, 256>>>(W_mlp,  KIN,   D_MOD, Wmh, Wml);
    wsplit_kernel<<<(D_MOD * QKV_N + 255) / 256, 256>>>(Wqkv,  D_MOD, QKV_N, Wqh, Wql);
    wsplit_kernel<<<(D_MOD * D_MOD + 255) / 256, 256>>>(Wproj, D_MOD, D_MOD, Wph, Wpl);
    wsplit_kernel<<<(D_MOD * D_FF + 255) / 256, 256>>>(W1,    D_MOD, D_FF,  W1h, W1l);
    wsplit_kernel<<<(D_FF * D_MOD + 255) / 256, 256>>>(W2,    D_FF,  D_MOD, W2h, W2l);

    // 1) conv (im2col + MMA GEMM), buffer then spa_position
    im2col_split<<<(BA * CCH * PIX) / 256, 256>>>(buffer, Ah, Al);
    gemm_mma<<<dim3(D_MOD / 64, TOK_M / 128), 256, GSM_TOTAL>>>(
        Ah, Al, Wmh, Wml, T, TOK_M, D_MOD, KIN, nullptr, nullptr, 0, nullptr, nullptr);
    im2col_split<<<(BA * CCH * PIX) / 256, 256>>>(spa_pos, Ah, Al);
    gemm_mma<<<dim3(D_MOD / 64, TOK_M / 128), 256, GSM_TOTAL>>>(
        Ah, Al, Wmh, Wml, PE, TOK_M, D_MOD, KIN, nullptr, nullptr, 0, nullptr, nullptr);

    // 2) x = LN(T + PE) -> bf16 hi/lo
    ln_kernel<<<TOK_M, 256>>>(T, PE, g1, b1, Xh, Xl);

    // 3) qkv
    gemm_mma<<<dim3(QKV_N / 64, TOK_M / 128), 256, GSM_TOTAL>>>(
        Xh, Xl, Wqh, Wql, QKV, TOK_M, QKV_N, D_MOD, nullptr, nullptr, 0, nullptr, nullptr);

    // 4) attention
    attn_kernel<<<PIX, 256, ATT_SMEM_BYTES>>>(QKV, AO, Wl, bl, Ww, bw, lamb);

    // 5) proj: S2 = AO @ Wproj + bproj + T
    split_kernel<<<(TOK_M * D_MOD + 255) / 256, 256>>>(AO, (size_t)TOK_M * D_MOD, AOh, AOl);
    gemm_mma<<<dim3(D_MOD / 64, TOK_M / 128), 256, GSM_TOTAL>>>(
        AOh, AOl, Wph, Wpl, S2, TOK_M, D_MOD, D_MOD, bproj, T, 0, nullptr, nullptr);

    // 6) y = LN(S2) -> hi/lo
    ln_kernel<<<TOK_M, 256>>>(S2, nullptr, g2, b2, Yh, Yl);

    // 7) FF: relu(y@W1) -> hi/lo directly; then @W2 + S2 -> XF
    gemm_mma<<<dim3(D_FF / 64, TOK_M / 128), 256, GSM_TOTAL>>>(
        Yh, Yl, W1h, W1l, nullptr, TOK_M, D_FF, D_MOD, nullptr, nullptr, 1, Fh, Fl);
    gemm_mma<<<dim3(D_MOD / 64, TOK_M / 128), 256, GSM_TOTAL>>>(
        Fh, Fl, W2h, W2l, XF, TOK_M, D_MOD, D_FF, nullptr, S2, 0, nullptr, nullptr);

    // 8) Token2SAI + conv -> out
    t2s_kernel<<<dim3(PIX / 128, BA), 256>>>(XF, Wconv, out);
}

// round 6
// speedup vs baseline: 1.4230x; 1.4230x over previous
#include <cuda_runtime.h>
#include <cuda_bf16.h>
#include <stdint.h>
#include <math.h>

// ---------------------------------------------------------------------------
// Problem constants: b=4, c=128, a=25, h=w=32
// Token order (this version): m = ba*1024 + p   (ba-major)
// Conv K order (this version): k = tap*128 + c
// ---------------------------------------------------------------------------
#define TOK_M   102400
#define D_MOD   256
#define D_FF    512
#define QKV_N   768
#define BA      100
#define PIX     1024
#define CCH     128
#define AA      25
#define KIN     1152

// ------------------------- scratch (static device) -------------------------
__device__ float g_T  [TOK_M * D_MOD];
__device__ float g_PE [TOK_M * D_MOD];
__device__ float g_QKV[TOK_M * QKV_N];
__device__ float g_AO [TOK_M * D_MOD];
__device__ float g_S2 [TOK_M * D_MOD];
__device__ float g_XF [TOK_M * D_MOD];

__device__ __nv_bfloat16 gA_hi[(size_t)TOK_M * KIN];
__device__ __nv_bfloat16 gA_lo[(size_t)TOK_M * KIN];
__device__ __nv_bfloat16 gX_hi[TOK_M * D_MOD],  gX_lo[TOK_M * D_MOD];
__device__ __nv_bfloat16 gAO_hi[TOK_M * D_MOD], gAO_lo[TOK_M * D_MOD];
__device__ __nv_bfloat16 gY_hi[TOK_M * D_MOD],  gY_lo[TOK_M * D_MOD];
__device__ __nv_bfloat16 gF_hi[TOK_M * D_FF],   gF_lo[TOK_M * D_FF];

__device__ __nv_bfloat16 gWmlp_hi [D_MOD * KIN],   gWmlp_lo [D_MOD * KIN];
__device__ __nv_bfloat16 gWqkv_hi [QKV_N * D_MOD], gWqkv_lo [QKV_N * D_MOD];
__device__ __nv_bfloat16 gWproj_hi[D_MOD * D_MOD], gWproj_lo[D_MOD * D_MOD];
__device__ __nv_bfloat16 gW1_hi   [D_FF * D_MOD],  gW1_lo   [D_FF * D_MOD];
__device__ __nv_bfloat16 gW2_hi   [D_MOD * D_FF],  gW2_lo   [D_MOD * D_FF];

// ---------------------------------------------------------------------------
// base-target-legal PTX helpers (sm_80+): mma.sync, ldmatrix, cp.async
// ---------------------------------------------------------------------------
__device__ __forceinline__ uint32_t smem_u32(const void* p) {
    uint32_t a;
    asm("{ .reg .u64 t; cvta.to.shared.u64 t, %1; cvt.u32.u64 %0, t; }"
        : "=r"(a) : "l"(p));
    return a;
}
__device__ __forceinline__ void ldsm_x4(uint32_t* r, uint32_t addr) {
    asm volatile("ldmatrix.sync.aligned.m8n8.x4.shared.b16 {%0,%1,%2,%3}, [%4];"
        : "=r"(r[0]), "=r"(r[1]), "=r"(r[2]), "=r"(r[3]) : "r"(addr));
}
__device__ __forceinline__ void ldsm_x2(uint32_t* r, uint32_t addr) {
    asm volatile("ldmatrix.sync.aligned.m8n8.x2.shared.b16 {%0,%1}, [%2];"
        : "=r"(r[0]), "=r"(r[1]) : "r"(addr));
}
__device__ __forceinline__ void mma16816(float* c, const uint32_t* a, const uint32_t* b) {
    asm volatile(
        "mma.sync.aligned.m16n8k16.row.col.f32.bf16.bf16.f32 "
        "{%0,%1,%2,%3}, {%4,%5,%6,%7}, {%8,%9}, {%0,%1,%2,%3};"
        : "+f"(c[0]), "+f"(c[1]), "+f"(c[2]), "+f"(c[3])
        : "r"(a[0]), "r"(a[1]), "r"(a[2]), "r"(a[3]), "r"(b[0]), "r"(b[1]));
}
#define CP16(dst, src) \
    asm volatile("cp.async.cg.shared.global [%0], [%1], 16;" \
        :: "r"(dst), "l"(src) : "memory")
#define CP_COMMIT() asm volatile("cp.async.commit_group;" ::: "memory")
#define CP_WAIT0()  asm volatile("cp.async.wait_group 0;" ::: "memory")
#define CP_WAIT1()  asm volatile("cp.async.wait_group 1;" ::: "memory")

// ---------------------------------------------------------------------------
// bf16x3 HMMA GEMM: C[M,N] = Ahi@Bt_hi^T + Ahi@Bt_lo^T + Alo@Bt_hi^T
// Tile BM=128, BN=64, BK=32; 256 threads = 8 warps (4m x 2n), warp 32x32.
// 3-stage cp.async pipeline, ONE __syncthreads per chunk.
// ---------------------------------------------------------------------------
#define RS 40                     // smem row stride in bf16
#define SM_AH 0                   // 128*40*2 = 10240 B
#define SM_AL 10240
#define SM_BH 20480               // 64*40*2 = 5120 B
#define SM_BL 25600
#define SM_BUF 30720              // per-stage bytes
#define GSM_TOTAL (3 * SM_BUF)    // 92160

__global__ __launch_bounds__(256) void gemm_mma(
    const __nv_bfloat16* __restrict__ Ahi, const __nv_bfloat16* __restrict__ Alo,
    const __nv_bfloat16* __restrict__ Bhi, const __nv_bfloat16* __restrict__ Blo,
    float* __restrict__ C, int M, int N, int K,
    const float* __restrict__ bias, const float* __restrict__ resid, int relu,
    __nv_bfloat16* __restrict__ Ohi, __nv_bfloat16* __restrict__ Olo)
{
    extern __shared__ char sm[];
    const uint32_t smb = smem_u32(sm);
    const int tid = threadIdx.x;
    const int lane = tid & 31;
    const int wid = tid >> 5;
    const int warpm = wid & 3;
    const int warpn = wid >> 2;
    const int m0 = blockIdx.y * 128;
    const int n0 = blockIdx.x * 64;

    // ---- loader geometry ----
    const int arow = tid >> 1;
    const int aseg = tid & 1;
    const uint32_t a_sm_off = (uint32_t)arow * (RS * 2) + aseg * 32;
    const __nv_bfloat16* pAh = Ahi + (size_t)(m0 + arow) * K + aseg * 16;
    const __nv_bfloat16* pAl = Alo + (size_t)(m0 + arow) * K + aseg * 16;

    const int bt   = tid & 127;
    const int brow = bt >> 1;
    const int bseg = bt & 1;
    const uint32_t b_sm_off = (uint32_t)brow * (RS * 2) + bseg * 32;
    const int is_blo = (tid >= 128);
    const __nv_bfloat16* pB =
        (is_blo ? Blo : Bhi) + (size_t)(n0 + brow) * K + bseg * 16;
    const uint32_t b_sm_base = is_blo ? SM_BL : SM_BH;

    const int nch = K >> 5;

    // prologue: chunks 0,1 -> stages 0,1 (separate groups)
#pragma unroll
    for (int pt = 0; pt < 2; pt++) {
        const uint32_t stg = (uint32_t)pt * SM_BUF;
        const size_t kc = (size_t)pt * 32;
        CP16(smb + stg + SM_AH + a_sm_off,      pAh + kc);
        CP16(smb + stg + SM_AH + a_sm_off + 16, pAh + kc + 8);
        CP16(smb + stg + SM_AL + a_sm_off,      pAl + kc);
        CP16(smb + stg + SM_AL + a_sm_off + 16, pAl + kc + 8);
        CP16(smb + stg + b_sm_base + b_sm_off,      pB + kc);
        CP16(smb + stg + b_sm_base + b_sm_off + 16, pB + kc + 8);
        CP_COMMIT();
    }

    float acc[2][4][4];
#pragma unroll
    for (int im = 0; im < 2; im++)
#pragma unroll
        for (int in = 0; in < 4; in++)
#pragma unroll
            for (int r = 0; r < 4; r++) acc[im][in][r] = 0.f;

    const uint32_t a_ld_row = (uint32_t)(warpm * 32 + (lane & 15));
    const uint32_t a_ld_k8  = (uint32_t)((lane >> 4) * 8);
    const int l15 = lane & 15;
    const uint32_t b_ld_row = (uint32_t)(warpn * 32 + (l15 & 7));
    const uint32_t b_ld_k8  = (uint32_t)(((l15 >> 3) & 1) * 8);

    int sc = 0;   // compute stage
    for (int t = 0; t < nch; t++) {
        if (t + 1 < nch) { CP_WAIT1(); } else { CP_WAIT0(); }
        __syncthreads();

        // issue chunk t+2 into stage (sc+2)%3 (read completed at iter t-1)
        if (t + 2 < nch) {
            const int si = (sc >= 1) ? sc - 1 : 2;
            const uint32_t stg = (uint32_t)si * SM_BUF;
            const size_t kc = (size_t)(t + 2) * 32;
            CP16(smb + stg + SM_AH + a_sm_off,      pAh + kc);
            CP16(smb + stg + SM_AH + a_sm_off + 16, pAh + kc + 8);
            CP16(smb + stg + SM_AL + a_sm_off,      pAl + kc);
            CP16(smb + stg + SM_AL + a_sm_off + 16, pAl + kc + 8);
            CP16(smb + stg + b_sm_base + b_sm_off,      pB + kc);
            CP16(smb + stg + b_sm_base + b_sm_off + 16, pB + kc + 8);
            CP_COMMIT();
        }

        const uint32_t cur = (uint32_t)sc * SM_BUF;
#pragma unroll
        for (int ks = 0; ks < 2; ks++) {
            uint32_t ah[2][4], al[2][4], bh[4][2], bl[4][2];
#pragma unroll
            for (int im = 0; im < 2; im++) {
                const uint32_t ao = cur +
                    ((a_ld_row + im * 16) * RS + ks * 16 + a_ld_k8) * 2;
                ldsm_x4(ah[im], smb + SM_AH + ao);
                ldsm_x4(al[im], smb + SM_AL + ao);
            }
#pragma unroll
            for (int in = 0; in < 4; in++) {
                const uint32_t bo = cur +
                    ((b_ld_row + in * 8) * RS + ks * 16 + b_ld_k8) * 2;
                ldsm_x2(bh[in], smb + SM_BH + bo);
                ldsm_x2(bl[in], smb + SM_BL + bo);
            }
#pragma unroll
            for (int im = 0; im < 2; im++)
#pragma unroll
                for (int in = 0; in < 4; in++) {
                    mma16816(acc[im][in], ah[im], bh[in]);
                    mma16816(acc[im][in], ah[im], bl[in]);
                    mma16816(acc[im][in], al[im], bh[in]);
                }
        }
        sc = (sc >= 2) ? 0 : sc + 1;
    }

    // ---- epilogue ----
#pragma unroll
    for (int im = 0; im < 2; im++) {
#pragma unroll
        for (int in = 0; in < 4; in++) {
            const int mrow = m0 + warpm * 32 + im * 16 + (lane >> 2);
            const int ncol = n0 + warpn * 32 + in * 8 + (lane & 3) * 2;
#pragma unroll
            for (int r = 0; r < 2; r++) {
                const int m = mrow + r * 8;
                float v0 = acc[im][in][r * 2 + 0];
                float v1 = acc[im][in][r * 2 + 1];
                if (bias)  { v0 += bias[ncol]; v1 += bias[ncol + 1]; }
                if (relu)  { v0 = fmaxf(v0, 0.f); v1 = fmaxf(v1, 0.f); }
                if (resid) {
                    const float* rp = resid + (size_t)m * N + ncol;
                    v0 += rp[0]; v1 += rp[1];
                }
                if (C) {
                    float2 f2; f2.x = v0; f2.y = v1;
                    *(float2*)(C + (size_t)m * N + ncol) = f2;
                }
                if (Ohi) {
                    __nv_bfloat16 h0 = __float2bfloat16_rn(v0);
                    __nv_bfloat16 h1 = __float2bfloat16_rn(v1);
                    __nv_bfloat162 hv; hv.x = h0; hv.y = h1;
                    __nv_bfloat162 lv;
                    lv.x = __float2bfloat16_rn(v0 - __bfloat162float(h0));
                    lv.y = __float2bfloat16_rn(v1 - __bfloat162float(h1));
                    *(__nv_bfloat162*)(Ohi + (size_t)m * N + ncol) = hv;
                    *(__nv_bfloat162*)(Olo + (size_t)m * N + ncol) = lv;
                }
            }
        }
    }
}

// ---------------------------------------------------------------------------
// weight transpose + split (generic): W [K,N] fp32 -> Bt [N,K] bf16 hi/lo
// ---------------------------------------------------------------------------
__global__ void wsplit_kernel(const float* __restrict__ W, int K, int N,
                              __nv_bfloat16* __restrict__ oh,
                              __nv_bfloat16* __restrict__ ol)
{
    const int idx = blockIdx.x * 256 + threadIdx.x;
    if (idx >= K * N) return;
    const int k = idx / N, n = idx - k * N;
    const float v = W[idx];
    const __nv_bfloat16 h = __float2bfloat16_rn(v);
    oh[(size_t)n * K + k] = h;
    ol[(size_t)n * K + k] = __float2bfloat16_rn(v - __bfloat162float(h));
}

// W_mlp variant: source k = c*9+tap, dest k' = tap*128+c
__global__ void wsplit_mlp(const float* __restrict__ W,
                           __nv_bfloat16* __restrict__ oh,
                           __nv_bfloat16* __restrict__ ol)
{
    const int idx = blockIdx.x * 256 + threadIdx.x;
    if (idx >= KIN * D_MOD) return;
    const int kk = idx / D_MOD, n = idx - kk * D_MOD;
    const int c = kk / 9, tap = kk - c * 9;
    const int kp = tap * 128 + c;
    const float v = W[idx];
    const __nv_bfloat16 h = __float2bfloat16_rn(v);
    oh[(size_t)n * KIN + kp] = h;
    ol[(size_t)n * KIN + kp] = __float2bfloat16_rn(v - __bfloat162float(h));
}

// ---------------------------------------------------------------------------
// elementwise split: X fp32 -> hi/lo bf16
// ---------------------------------------------------------------------------
__global__ void split_kernel(const float* __restrict__ X, size_t n,
                             __nv_bfloat16* __restrict__ oh,
                             __nv_bfloat16* __restrict__ ol)
{
    const size_t i = (size_t)blockIdx.x * 256 + threadIdx.x;
    if (i >= n) return;
    const float v = X[i];
    const __nv_bfloat16 h = __float2bfloat16_rn(v);
    oh[i] = h;
    ol[i] = __float2bfloat16_rn(v - __bfloat162float(h));
}

// ---------------------------------------------------------------------------
// im2col v2 (coalesced): A[m = ba*1024+p][k = tap*128+c] bf16 hi/lo.
// Block = (pblk of 8 image rows, cblk of 32 channels, ba). smem-staged.
// grid (4, 4, 100), 256 threads.
// ---------------------------------------------------------------------------
__global__ __launch_bounds__(256) void im2col2(
    const float* __restrict__ src,
    __nv_bfloat16* __restrict__ Ahi, __nv_bfloat16* __restrict__ Alo)
{
    __shared__ float xs[32 * 321];      // [c][10 rows * 32 + pad]
    const int tid = threadIdx.x;
    const int i0 = blockIdx.x * 8;      // image rows i0..i0+7
    const int c0 = blockIdx.y * 32;
    const int ba = blockIdx.z;
    const int b_ = ba / AA, a_ = ba - b_ * AA;

    // load 10 rows (i0-1..i0+8) x 32 cols x 32 channels, zero-padded rows
    for (int l = tid; l < 10240; l += 256) {
        const int c = l / 320;
        const int rem = l - c * 320;
        const int r = rem >> 5, col = rem & 31;
        const int ii = i0 - 1 + r;
        float v = 0.f;
        if (ii >= 0 && ii < 32)
            v = src[(((size_t)(b_ * CCH + c0 + c)) * AA + a_) * PIX + ii * 32 + col];
        xs[c * 321 + rem] = v;
    }
    __syncthreads();

    // write phase: warp w owns image row i0+w; lane = channel.
    const int w = tid >> 5, lane = tid & 31;
    const int i = i0 + w;
    const float* xrow = xs + lane * 321;
    for (int j = 0; j < 32; j++) {
        const size_t m = (size_t)ba * PIX + i * 32 + j;
        const size_t mbase = m * KIN + c0 + lane;
#pragma unroll
        for (int tap = 0; tap < 9; tap++) {
            const int di = tap / 3, dj = tap - di * 3 - 1;
            const int jj = j + dj;
            float v = 0.f;
            if (jj >= 0 && jj < 32) v = xrow[(w + di) * 32 + jj];
            const __nv_bfloat16 h = __float2bfloat16_rn(v);
            Ahi[mbase + (size_t)tap * 128] = h;
            Alo[mbase + (size_t)tap * 128] =
                __float2bfloat16_rn(v - __bfloat162float(h));
        }
    }
}

// ---------------------------------------------------------------------------
// LayerNorm over D=256 -> bf16 hi/lo. Optional addsrc.
// ---------------------------------------------------------------------------
__global__ __launch_bounds__(256) void ln_kernel(
    const float* __restrict__ X, const float* __restrict__ addsrc,
    const float* __restrict__ g, const float* __restrict__ b,
    __nv_bfloat16* __restrict__ oh, __nv_bfloat16* __restrict__ ol)
{
    const size_t row = blockIdx.x;
    const int tid = threadIdx.x;
    __shared__ float red[8];

    float v = X[row * D_MOD + tid];
    if (addsrc) v += addsrc[row * D_MOD + tid];

    float s = v;
#pragma unroll
    for (int o = 16; o; o >>= 1) s += __shfl_xor_sync(0xffffffffu, s, o);
    if ((tid & 31) == 0) red[tid >> 5] = s;
    __syncthreads();
    float mean = 0.f;
#pragma unroll
    for (int i = 0; i < 8; i++) mean += red[i];
    mean *= (1.f / 256.f);
    __syncthreads();

    const float dev = v - mean;
    float q = dev * dev;
#pragma unroll
    for (int o = 16; o; o >>= 1) q += __shfl_xor_sync(0xffffffffu, q, o);
    if ((tid & 31) == 0) red[tid >> 5] = q;
    __syncthreads();
    float var = 0.f;
#pragma unroll
    for (int i = 0; i < 8; i++) var += red[i];
    var *= (1.f / 256.f);

    const float r = dev * rsqrtf(var + 1e-5f) * g[tid] + b[tid];
    const __nv_bfloat16 h = __float2bfloat16_rn(r);
    oh[row * D_MOD + tid] = h;
    ol[row * D_MOD + tid] = __float2bfloat16_rn(r - __bfloat162float(h));
}

// ---------------------------------------------------------------------------
// Fused attention (ba-major rows: token (p, ba) at row ba*1024 + p)
// ---------------------------------------------------------------------------
#define ATT_SMEM_FLOATS (25600 + 25600 + 256 + 800 + 800 + 64 + 64 + 8 + 8 + 8)
#define ATT_SMEM_BYTES  (ATT_SMEM_FLOATS * 4)

__global__ __launch_bounds__(256) void attn_kernel(
    const float* __restrict__ qkv, float* __restrict__ out,
    const float* __restrict__ Wl, const float* __restrict__ bl,
    const float* __restrict__ Ww, const float* __restrict__ bw,
    const float* __restrict__ lamb)
{
    extern __shared__ float smf[];
    float* Ks   = smf;
    float* Vs   = Ks + 25600;
    float* qs   = Vs + 25600;
    float* sraw = qs + 256;
    float* satt = sraw + 800;
    float* swl  = satt + 800;
    float* sww  = swl + 64;
    float* sbl  = sww + 64;
    float* sbw  = sbl + 8;
    float* slam = sbw + 8;

    const int tid = threadIdx.x;
    const int bq = blockIdx.x;      // pixel
    const float scale = 0.17677669529663687f;

    if (tid < 64) { swl[tid] = Wl[tid]; sww[tid] = Ww[tid]; }
    if (tid < 8)  { sbl[tid] = bl[tid]; sbw[tid] = bw[tid]; slam[tid] = lamb[tid]; }

    for (int idx = tid; idx < 25600; idx += 256) {
        const int m = idx >> 8, cc = idx & 255;
        const size_t rowb = ((size_t)m * PIX + bq) * QKV_N;
        Ks[idx] = qkv[rowb + 256 + cc];
        Vs[idx] = qkv[rowb + 512 + cc];
    }
    __syncthreads();

    const int g = tid >> 5, lane = tid & 31;

    for (int n = 0; n < BA; n++) {
        qs[tid] = qkv[((size_t)n * PIX + bq) * QKV_N + tid] * scale;
        __syncthreads();

        for (int e = tid; e < 800; e += 256) {
            const int h = e / 100, m = e - h * 100;
            const float* kp = Ks + m * 256 + h * 32;
            const float* qp = qs + h * 32;
            float d = 0.f;
#pragma unroll
            for (int dd = 0; dd < 32; dd++) d += qp[dd] * kp[dd];
            sraw[e] = d;
        }
        __syncthreads();

        for (int e = tid; e < 800; e += 256) {
            const int gg = e / 100, m = e - gg * 100;
            float s = sbl[gg];
#pragma unroll
            for (int h = 0; h < 8; h++) s += sraw[h * 100 + m] * swl[gg * 8 + h];
            satt[e] = s;
        }
        __syncthreads();

        {
            float mx = -1e30f;
            for (int m = lane; m < 100; m += 32) mx = fmaxf(mx, satt[g * 100 + m]);
#pragma unroll
            for (int o = 16; o; o >>= 1) mx = fmaxf(mx, __shfl_xor_sync(0xffffffffu, mx, o));
            float sum = 0.f;
            for (int m = lane; m < 100; m += 32) {
                const float e2 = __expf(satt[g * 100 + m] - mx);
                sraw[g * 100 + m] = e2;
                sum += e2;
            }
#pragma unroll
            for (int o = 16; o; o >>= 1) sum += __shfl_xor_sync(0xffffffffu, sum, o);
            const float inv = 1.f / sum;
            for (int m = lane; m < 100; m += 32) sraw[g * 100 + m] *= inv;
        }
        __syncthreads();

        for (int e = tid; e < 800; e += 256) {
            const int gg = e / 100, m = e - gg * 100;
            float s = sbw[gg];
#pragma unroll
            for (int h = 0; h < 8; h++) s += sraw[h * 100 + m] * sww[gg * 8 + h];
            s = 0.01f + (s - 0.01f) * (1.f + slam[gg]);
            satt[e] = s;
        }
        __syncthreads();

        {
            const int d = lane;
            float o = 0.f;
            const float* vp = Vs + g * 32 + d;
            const float* ap = satt + g * 100;
#pragma unroll 4
            for (int m = 0; m < 100; m++) o += ap[m] * vp[m * 256];
            out[((size_t)n * PIX + bq) * D_MOD + g * 32 + d] = o;
        }
        __syncthreads();
    }
}

// ---------------------------------------------------------------------------
// Token2SAI + 1x1x1 conv (ba-major rows)
// ---------------------------------------------------------------------------
__global__ __launch_bounds__(256) void t2s_kernel(
    const float* __restrict__ F, const float* __restrict__ Wc,
    float* __restrict__ out)
{
    __shared__ float Wt[8 * 128];
    __shared__ float Fs[8 * 128];
    const int tid = threadIdx.x;
    const int p0 = blockIdx.x * 128;
    const int ba = blockIdx.y;
    const int b_ = ba / AA, a_ = ba - b_ * AA;
    const int tx = tid & 15;
    const int ty = tid >> 4;

    float acc[8][8];
#pragma unroll
    for (int i = 0; i < 8; i++)
#pragma unroll
        for (int j = 0; j < 8; j++) acc[i][j] = 0.f;

    const int wrow = tid >> 1, wcol = (tid & 1) * 4;

    for (int k0 = 0; k0 < D_MOD; k0 += 8) {
        float4 wv = *(const float4*)(Wc + (size_t)wrow * D_MOD + k0 + wcol);
        Wt[(wcol + 0) * 128 + wrow] = wv.x;
        Wt[(wcol + 1) * 128 + wrow] = wv.y;
        Wt[(wcol + 2) * 128 + wrow] = wv.z;
        Wt[(wcol + 3) * 128 + wrow] = wv.w;
        float4 fv = *(const float4*)(F + ((size_t)ba * PIX + p0 + wrow) * D_MOD + k0 + wcol);
        Fs[(wcol + 0) * 128 + wrow] = fv.x;
        Fs[(wcol + 1) * 128 + wrow] = fv.y;
        Fs[(wcol + 2) * 128 + wrow] = fv.z;
        Fs[(wcol + 3) * 128 + wrow] = fv.w;
        __syncthreads();
#pragma unroll
        for (int kk = 0; kk < 8; kk++) {
            float a[8], b[8];
            *(float4*)(a)     = *(const float4*)&Wt[kk * 128 + ty * 8];
            *(float4*)(a + 4) = *(const float4*)&Wt[kk * 128 + ty * 8 + 4];
            *(float4*)(b)     = *(const float4*)&Fs[kk * 128 + tx * 8];
            *(float4*)(b + 4) = *(const float4*)&Fs[kk * 128 + tx * 8 + 4];
#pragma unroll
            for (int i = 0; i < 8; i++)
#pragma unroll
                for (int j = 0; j < 8; j++) acc[i][j] += a[i] * b[j];
        }
        __syncthreads();
    }

#pragma unroll
    for (int i = 0; i < 8; i++) {
        const int o = ty * 8 + i;
        float* op = out + ((size_t)(b_ * CCH + o) * AA + a_) * PIX + p0 + tx * 8;
        *(float4*)(op)     = *(float4*)(acc[i]);
        *(float4*)(op + 4) = *(float4*)(acc[i] + 4);
    }
}

// ---------------------------------------------------------------------------
extern "C" void kernel_launch(void* const* d_in, const int* in_sizes, int n_in,
                              void* d_out, int out_size)
{
    const float* buffer  = (const float*)d_in[0];
    const float* spa_pos = (const float*)d_in[1];
    const float* W_mlp   = (const float*)d_in[2];
    const float* g1      = (const float*)d_in[3];
    const float* b1      = (const float*)d_in[4];
    const float* Wqkv    = (const float*)d_in[5];
    const float* Wproj   = (const float*)d_in[6];
    const float* bproj   = (const float*)d_in[7];
    const float* Wl      = (const float*)d_in[8];
    const float* bl      = (const float*)d_in[9];
    const float* Ww      = (const float*)d_in[10];
    const float* bw      = (const float*)d_in[11];
    const float* lamb    = (const float*)d_in[12];
    const float* g2      = (const float*)d_in[13];
    const float* b2      = (const float*)d_in[14];
    const float* W1      = (const float*)d_in[15];
    const float* W2      = (const float*)d_in[16];
    const float* Wconv   = (const float*)d_in[17];
    float* out = (float*)d_out;

    float *T, *PE, *QKV, *AO, *S2, *XF;
    cudaGetSymbolAddress((void**)&T,   g_T);
    cudaGetSymbolAddress((void**)&PE,  g_PE);
    cudaGetSymbolAddress((void**)&QKV, g_QKV);
    cudaGetSymbolAddress((void**)&AO,  g_AO);
    cudaGetSymbolAddress((void**)&S2,  g_S2);
    cudaGetSymbolAddress((void**)&XF,  g_XF);

    __nv_bfloat16 *Ah, *Al, *Xh, *Xl, *AOh, *AOl, *Yh, *Yl, *Fh, *Fl;
    __nv_bfloat16 *Wmh, *Wml, *Wqh, *Wql, *Wph, *Wpl, *W1h, *W1l, *W2h, *W2l;
    cudaGetSymbolAddress((void**)&Ah,  gA_hi);   cudaGetSymbolAddress((void**)&Al,  gA_lo);
    cudaGetSymbolAddress((void**)&Xh,  gX_hi);   cudaGetSymbolAddress((void**)&Xl,  gX_lo);
    cudaGetSymbolAddress((void**)&AOh, gAO_hi);  cudaGetSymbolAddress((void**)&AOl, gAO_lo);
    cudaGetSymbolAddress((void**)&Yh,  gY_hi);   cudaGetSymbolAddress((void**)&Yl,  gY_lo);
    cudaGetSymbolAddress((void**)&Fh,  gF_hi);   cudaGetSymbolAddress((void**)&Fl,  gF_lo);
    cudaGetSymbolAddress((void**)&Wmh, gWmlp_hi);  cudaGetSymbolAddress((void**)&Wml, gWmlp_lo);
    cudaGetSymbolAddress((void**)&Wqh, gWqkv_hi);  cudaGetSymbolAddress((void**)&Wql, gWqkv_lo);
    cudaGetSymbolAddress((void**)&Wph, gWproj_hi); cudaGetSymbolAddress((void**)&Wpl, gWproj_lo);
    cudaGetSymbolAddress((void**)&W1h, gW1_hi);    cudaGetSymbolAddress((void**)&W1l, gW1_lo);
    cudaGetSymbolAddress((void**)&W2h, gW2_hi);    cudaGetSymbolAddress((void**)&W2l, gW2_lo);

    cudaFuncSetAttribute(attn_kernel, cudaFuncAttributeMaxDynamicSharedMemorySize,
                         ATT_SMEM_BYTES);
    cudaFuncSetAttribute(gemm_mma, cudaFuncAttributeMaxDynamicSharedMemorySize,
                         GSM_TOTAL);

    // Launch order chosen so launch #6 (ncu -s 5 -c 1 capture) = conv GEMM.
    // 1
    im2col2<<<dim3(4, 4, BA), 256>>>(buffer, Ah, Al);
    // 2-5
    wsplit_mlp<<<(KIN * D_MOD + 255) / 256, 256>>>(W_mlp, Wmh, Wml);
    wsplit_kernel<<<(D_MOD * QKV_N + 255) / 256, 256>>>(Wqkv,  D_MOD, QKV_N, Wqh, Wql);
    wsplit_kernel<<<(D_MOD * D_MOD + 255) / 256, 256>>>(Wproj, D_MOD, D_MOD, Wph, Wpl);
    wsplit_kernel<<<(D_MOD * D_FF + 255) / 256, 256>>>(W1,    D_MOD, D_FF,  W1h, W1l);
    // 6  <-- ncu capture target
    gemm_mma<<<dim3(D_MOD / 64, TOK_M / 128), 256, GSM_TOTAL>>>(
        Ah, Al, Wmh, Wml, T, TOK_M, D_MOD, KIN, nullptr, nullptr, 0, nullptr, nullptr);
    // 7
    wsplit_kernel<<<(D_FF * D_MOD + 255) / 256, 256>>>(W2, D_FF, D_MOD, W2h, W2l);
    // 8-9
    im2col2<<<dim3(4, 4, BA), 256>>>(spa_pos, Ah, Al);
    gemm_mma<<<dim3(D_MOD / 64, TOK_M / 128), 256, GSM_TOTAL>>>(
        Ah, Al, Wmh, Wml, PE, TOK_M, D_MOD, KIN, nullptr, nullptr, 0, nullptr, nullptr);

    // x = LN(T + PE) -> hi/lo
    ln_kernel<<<TOK_M, 256>>>(T, PE, g1, b1, Xh, Xl);

    // qkv
    gemm_mma<<<dim3(QKV_N / 64, TOK_M / 128), 256, GSM_TOTAL>>>(
        Xh, Xl, Wqh, Wql, QKV, TOK_M, QKV_N, D_MOD, nullptr, nullptr, 0, nullptr, nullptr);

    // attention
    attn_kernel<<<PIX, 256, ATT_SMEM_BYTES>>>(QKV, AO, Wl, bl, Ww, bw, lamb);

    // proj: S2 = AO @ Wproj + bproj + T
    split_kernel<<<(TOK_M * D_MOD + 255) / 256, 256>>>(AO, (size_t)TOK_M * D_MOD, AOh, AOl);
    gemm_mma<<<dim3(D_MOD / 64, TOK_M / 128), 256, GSM_TOTAL>>>(
        AOh, AOl, Wph, Wpl, S2, TOK_M, D_MOD, D_MOD, bproj, T, 0, nullptr, nullptr);

    // y = LN(S2) -> hi/lo
    ln_kernel<<<TOK_M, 256>>>(S2, nullptr, g2, b2, Yh, Yl);

    // FF
    gemm_mma<<<dim3(D_FF / 64, TOK_M / 128), 256, GSM_TOTAL>>>(
        Yh, Yl, W1h, W1l, nullptr, TOK_M, D_FF, D_MOD, nullptr, nullptr, 1, Fh, Fl);
    gemm_mma<<<dim3(D_MOD / 64, TOK_M / 128), 256, GSM_TOTAL>>>(
        Fh, Fl, W2h, W2l, XF, TOK_M, D_MOD, D_FF, nullptr, S2, 0, nullptr, nullptr);

    // Token2SAI + conv -> out
    t2s_kernel<<<dim3(PIX / 128, BA), 256>>>(XF, Wconv, out);
}

// round 7
// speedup vs baseline: 1.4909x; 1.0477x over previous
#include <cuda_runtime.h>
#include <cuda_bf16.h>
#include <stdint.h>
#include <math.h>

// ---------------------------------------------------------------------------
// Problem constants: b=4, c=128, a=25, h=w=32
// Token order: m = ba*1024 + p (ba-major). Conv K order: k = tap*128 + c.
// ---------------------------------------------------------------------------
#define TOK_M   102400
#define D_MOD   256
#define D_FF    512
#define QKV_N   768
#define BA      100
#define PIX     1024
#define CCH     128
#define AA      25
#define KIN     1152

// ------------------------- scratch (static device) -------------------------
__device__ float g_T  [TOK_M * D_MOD];
__device__ float g_PE [TOK_M * D_MOD];
__device__ float g_QKV[TOK_M * QKV_N];
__device__ float g_S2 [TOK_M * D_MOD];

__device__ __nv_bfloat16 gA_hi[(size_t)TOK_M * KIN];
__device__ __nv_bfloat16 gA_lo[(size_t)TOK_M * KIN];
__device__ __nv_bfloat16 gX_hi[TOK_M * D_MOD],  gX_lo[TOK_M * D_MOD];   // LN1 out; later XF hi/lo
__device__ __nv_bfloat16 gAO_hi[TOK_M * D_MOD], gAO_lo[TOK_M * D_MOD];
__device__ __nv_bfloat16 gY_hi[TOK_M * D_MOD],  gY_lo[TOK_M * D_MOD];
__device__ __nv_bfloat16 gF_hi[TOK_M * D_FF],   gF_lo[TOK_M * D_FF];

__device__ __nv_bfloat16 gWmlp_hi [D_MOD * KIN],   gWmlp_lo [D_MOD * KIN];
__device__ __nv_bfloat16 gWqkv_hi [QKV_N * D_MOD], gWqkv_lo [QKV_N * D_MOD];
__device__ __nv_bfloat16 gWproj_hi[D_MOD * D_MOD], gWproj_lo[D_MOD * D_MOD];
__device__ __nv_bfloat16 gW1_hi   [D_FF * D_MOD],  gW1_lo   [D_FF * D_MOD];
__device__ __nv_bfloat16 gW2_hi   [D_MOD * D_FF],  gW2_lo   [D_MOD * D_FF];
__device__ __nv_bfloat16 gWc_hi   [CCH * D_MOD],   gWc_lo   [CCH * D_MOD];

// ---------------------------------------------------------------------------
// base-target-legal PTX helpers (sm_80+)
// ---------------------------------------------------------------------------
__device__ __forceinline__ uint32_t smem_u32(const void* p) {
    uint32_t a;
    asm("{ .reg .u64 t; cvta.to.shared.u64 t, %1; cvt.u32.u64 %0, t; }"
        : "=r"(a) : "l"(p));
    return a;
}
__device__ __forceinline__ void ldsm_x4(uint32_t* r, uint32_t addr) {
    asm volatile("ldmatrix.sync.aligned.m8n8.x4.shared.b16 {%0,%1,%2,%3}, [%4];"
        : "=r"(r[0]), "=r"(r[1]), "=r"(r[2]), "=r"(r[3]) : "r"(addr));
}
__device__ __forceinline__ void ldsm_x2(uint32_t* r, uint32_t addr) {
    asm volatile("ldmatrix.sync.aligned.m8n8.x2.shared.b16 {%0,%1}, [%2];"
        : "=r"(r[0]), "=r"(r[1]) : "r"(addr));
}
__device__ __forceinline__ void mma16816(float* c, const uint32_t* a, const uint32_t* b) {
    asm volatile(
        "mma.sync.aligned.m16n8k16.row.col.f32.bf16.bf16.f32 "
        "{%0,%1,%2,%3}, {%4,%5,%6,%7}, {%8,%9}, {%0,%1,%2,%3};"
        : "+f"(c[0]), "+f"(c[1]), "+f"(c[2]), "+f"(c[3])
        : "r"(a[0]), "r"(a[1]), "r"(a[2]), "r"(a[3]), "r"(b[0]), "r"(b[1]));
}
#define CP16(dst, src) \
    asm volatile("cp.async.cg.shared.global [%0], [%1], 16;" \
        :: "r"(dst), "l"(src) : "memory")
#define CP_COMMIT() asm volatile("cp.async.commit_group;" ::: "memory")
#define CP_WAIT0()  asm volatile("cp.async.wait_group 0;" ::: "memory")
#define CP_WAIT1()  asm volatile("cp.async.wait_group 1;" ::: "memory")

// ---------------------------------------------------------------------------
// bf16x3 HMMA GEMM: C = Ahi@Bt_hi^T + Ahi@Bt_lo^T + Alo@Bt_hi^T
// BM=128, BN=64, BK=32; 256 threads = 8 warps (4m x 2n), warp 32x32.
// 3-stage cp.async pipeline, one __syncthreads per chunk.
// Epilogue: +bias, relu, +resid; outputs fp32 C, bf16 hi/lo, or SAI scatter.
// ---------------------------------------------------------------------------
#define RS 40
#define SM_AH 0
#define SM_AL 10240
#define SM_BH 20480
#define SM_BL 25600
#define SM_BUF 30720
#define GSM_TOTAL (3 * SM_BUF)

__global__ __launch_bounds__(256) void gemm_mma(
    const __nv_bfloat16* __restrict__ Ahi, const __nv_bfloat16* __restrict__ Alo,
    const __nv_bfloat16* __restrict__ Bhi, const __nv_bfloat16* __restrict__ Blo,
    float* __restrict__ C, int M, int N, int K,
    const float* __restrict__ bias, const float* __restrict__ resid, int relu,
    __nv_bfloat16* __restrict__ Ohi, __nv_bfloat16* __restrict__ Olo,
    float* __restrict__ sai)
{
    extern __shared__ char sm[];
    const uint32_t smb = smem_u32(sm);
    const int tid = threadIdx.x;
    const int lane = tid & 31;
    const int wid = tid >> 5;
    const int warpm = wid & 3;
    const int warpn = wid >> 2;
    const int m0 = blockIdx.y * 128;
    const int n0 = blockIdx.x * 64;

    const int arow = tid >> 1;
    const int aseg = tid & 1;
    const uint32_t a_sm_off = (uint32_t)arow * (RS * 2) + aseg * 32;
    const __nv_bfloat16* pAh = Ahi + (size_t)(m0 + arow) * K + aseg * 16;
    const __nv_bfloat16* pAl = Alo + (size_t)(m0 + arow) * K + aseg * 16;

    const int bt   = tid & 127;
    const int brow = bt >> 1;
    const int bseg = bt & 1;
    const uint32_t b_sm_off = (uint32_t)brow * (RS * 2) + bseg * 32;
    const int is_blo = (tid >= 128);
    const __nv_bfloat16* pB =
        (is_blo ? Blo : Bhi) + (size_t)(n0 + brow) * K + bseg * 16;
    const uint32_t b_sm_base = is_blo ? SM_BL : SM_BH;

    const int nch = K >> 5;

#pragma unroll
    for (int pt = 0; pt < 2; pt++) {
        const uint32_t stg = (uint32_t)pt * SM_BUF;
        const size_t kc = (size_t)pt * 32;
        CP16(smb + stg + SM_AH + a_sm_off,      pAh + kc);
        CP16(smb + stg + SM_AH + a_sm_off + 16, pAh + kc + 8);
        CP16(smb + stg + SM_AL + a_sm_off,      pAl + kc);
        CP16(smb + stg + SM_AL + a_sm_off + 16, pAl + kc + 8);
        CP16(smb + stg + b_sm_base + b_sm_off,      pB + kc);
        CP16(smb + stg + b_sm_base + b_sm_off + 16, pB + kc + 8);
        CP_COMMIT();
    }

    float acc[2][4][4];
#pragma unroll
    for (int im = 0; im < 2; im++)
#pragma unroll
        for (int in = 0; in < 4; in++)
#pragma unroll
            for (int r = 0; r < 4; r++) acc[im][in][r] = 0.f;

    const uint32_t a_ld_row = (uint32_t)(warpm * 32 + (lane & 15));
    const uint32_t a_ld_k8  = (uint32_t)((lane >> 4) * 8);
    const int l15 = lane & 15;
    const uint32_t b_ld_row = (uint32_t)(warpn * 32 + (l15 & 7));
    const uint32_t b_ld_k8  = (uint32_t)(((l15 >> 3) & 1) * 8);

    int sc = 0;
    for (int t = 0; t < nch; t++) {
        if (t + 1 < nch) { CP_WAIT1(); } else { CP_WAIT0(); }
        __syncthreads();

        if (t + 2 < nch) {
            const int si = (sc >= 1) ? sc - 1 : 2;
            const uint32_t stg = (uint32_t)si * SM_BUF;
            const size_t kc = (size_t)(t + 2) * 32;
            CP16(smb + stg + SM_AH + a_sm_off,      pAh + kc);
            CP16(smb + stg + SM_AH + a_sm_off + 16, pAh + kc + 8);
            CP16(smb + stg + SM_AL + a_sm_off,      pAl + kc);
            CP16(smb + stg + SM_AL + a_sm_off + 16, pAl + kc + 8);
            CP16(smb + stg + b_sm_base + b_sm_off,      pB + kc);
            CP16(smb + stg + b_sm_base + b_sm_off + 16, pB + kc + 8);
            CP_COMMIT();
        }

        const uint32_t cur = (uint32_t)sc * SM_BUF;
#pragma unroll
        for (int ks = 0; ks < 2; ks++) {
            uint32_t ah[2][4], al[2][4], bh[4][2], bl[4][2];
#pragma unroll
            for (int im = 0; im < 2; im++) {
                const uint32_t ao = cur +
                    ((a_ld_row + im * 16) * RS + ks * 16 + a_ld_k8) * 2;
                ldsm_x4(ah[im], smb + SM_AH + ao);
                ldsm_x4(al[im], smb + SM_AL + ao);
            }
#pragma unroll
            for (int in = 0; in < 4; in++) {
                const uint32_t bo = cur +
                    ((b_ld_row + in * 8) * RS + ks * 16 + b_ld_k8) * 2;
                ldsm_x2(bh[in], smb + SM_BH + bo);
                ldsm_x2(bl[in], smb + SM_BL + bo);
            }
#pragma unroll
            for (int im = 0; im < 2; im++)
#pragma unroll
                for (int in = 0; in < 4; in++) {
                    mma16816(acc[im][in], ah[im], bh[in]);
                    mma16816(acc[im][in], ah[im], bl[in]);
                    mma16816(acc[im][in], al[im], bh[in]);
                }
        }
        sc = (sc >= 2) ? 0 : sc + 1;
    }

    // ---- epilogue ----
#pragma unroll
    for (int im = 0; im < 2; im++) {
#pragma unroll
        for (int in = 0; in < 4; in++) {
            const int mrow = m0 + warpm * 32 + im * 16 + (lane >> 2);
            const int ncol = n0 + warpn * 32 + in * 8 + (lane & 3) * 2;
#pragma unroll
            for (int r = 0; r < 2; r++) {
                const int m = mrow + r * 8;
                float v0 = acc[im][in][r * 2 + 0];
                float v1 = acc[im][in][r * 2 + 1];
                if (bias)  { v0 += bias[ncol]; v1 += bias[ncol + 1]; }
                if (relu)  { v0 = fmaxf(v0, 0.f); v1 = fmaxf(v1, 0.f); }
                if (resid) {
                    const float* rp = resid + (size_t)m * N + ncol;
                    v0 += rp[0]; v1 += rp[1];
                }
                if (C) {
                    float2 f2; f2.x = v0; f2.y = v1;
                    *(float2*)(C + (size_t)m * N + ncol) = f2;
                }
                if (Ohi) {
                    __nv_bfloat16 h0 = __float2bfloat16_rn(v0);
                    __nv_bfloat16 h1 = __float2bfloat16_rn(v1);
                    __nv_bfloat162 hv; hv.x = h0; hv.y = h1;
                    __nv_bfloat162 lv;
                    lv.x = __float2bfloat16_rn(v0 - __bfloat162float(h0));
                    lv.y = __float2bfloat16_rn(v1 - __bfloat162float(h1));
                    *(__nv_bfloat162*)(Ohi + (size_t)m * N + ncol) = hv;
                    *(__nv_bfloat162*)(Olo + (size_t)m * N + ncol) = lv;
                }
                if (sai) {
                    // m = ba*1024+p, ncol = output channel o
                    const int ba = m >> 10, p = m & 1023;
                    const int b_ = ba / AA, a_ = ba - b_ * AA;
                    sai[((size_t)(b_ * CCH + ncol)     * AA + a_) * PIX + p] = v0;
                    sai[((size_t)(b_ * CCH + ncol + 1) * AA + a_) * PIX + p] = v1;
                }
            }
        }
    }
}

// ---------------------------------------------------------------------------
// weight transpose + split: W [K,N] fp32 -> Bt [N,K] bf16 hi/lo
// ---------------------------------------------------------------------------
__global__ void wsplit_kernel(const float* __restrict__ W, int K, int N,
                              __nv_bfloat16* __restrict__ oh,
                              __nv_bfloat16* __restrict__ ol)
{
    const int idx = blockIdx.x * 256 + threadIdx.x;
    if (idx >= K * N) return;
    const int k = idx / N, n = idx - k * N;
    const float v = W[idx];
    const __nv_bfloat16 h = __float2bfloat16_rn(v);
    oh[(size_t)n * K + k] = h;
    ol[(size_t)n * K + k] = __float2bfloat16_rn(v - __bfloat162float(h));
}

// W_mlp variant: source k = c*9+tap, dest k' = tap*128+c
__global__ void wsplit_mlp(const float* __restrict__ W,
                           __nv_bfloat16* __restrict__ oh,
                           __nv_bfloat16* __restrict__ ol)
{
    const int idx = blockIdx.x * 256 + threadIdx.x;
    if (idx >= KIN * D_MOD) return;
    const int kk = idx / D_MOD, n = idx - kk * D_MOD;
    const int c = kk / 9, tap = kk - c * 9;
    const int kp = tap * 128 + c;
    const float v = W[idx];
    const __nv_bfloat16 h = __float2bfloat16_rn(v);
    oh[(size_t)n * KIN + kp] = h;
    ol[(size_t)n * KIN + kp] = __float2bfloat16_rn(v - __bfloat162float(h));
}

// elementwise split (Wconv is already [N][K] -> no transpose)
__global__ void split_kernel(const float* __restrict__ X, size_t n,
                             __nv_bfloat16* __restrict__ oh,
                             __nv_bfloat16* __restrict__ ol)
{
    const size_t i = (size_t)blockIdx.x * 256 + threadIdx.x;
    if (i >= n) return;
    const float v = X[i];
    const __nv_bfloat16 h = __float2bfloat16_rn(v);
    oh[i] = h;
    ol[i] = __float2bfloat16_rn(v - __bfloat162float(h));
}

// ---------------------------------------------------------------------------
// im2col (coalesced): A[m = ba*1024+p][k = tap*128+c] bf16 hi/lo.
// ---------------------------------------------------------------------------
__global__ __launch_bounds__(256) void im2col2(
    const float* __restrict__ src,
    __nv_bfloat16* __restrict__ Ahi, __nv_bfloat16* __restrict__ Alo)
{
    __shared__ float xs[32 * 321];
    const int tid = threadIdx.x;
    const int i0 = blockIdx.x * 8;
    const int c0 = blockIdx.y * 32;
    const int ba = blockIdx.z;
    const int b_ = ba / AA, a_ = ba - b_ * AA;

    for (int l = tid; l < 10240; l += 256) {
        const int c = l / 320;
        const int rem = l - c * 320;
        const int r = rem >> 5, col = rem & 31;
        const int ii = i0 - 1 + r;
        float v = 0.f;
        if (ii >= 0 && ii < 32)
            v = src[(((size_t)(b_ * CCH + c0 + c)) * AA + a_) * PIX + ii * 32 + col];
        xs[c * 321 + rem] = v;
    }
    __syncthreads();

    const int w = tid >> 5, lane = tid & 31;
    const int i = i0 + w;
    const float* xrow = xs + lane * 321;
    for (int j = 0; j < 32; j++) {
        const size_t m = (size_t)ba * PIX + i * 32 + j;
        const size_t mbase = m * KIN + c0 + lane;
#pragma unroll
        for (int tap = 0; tap < 9; tap++) {
            const int di = tap / 3, dj = tap - di * 3 - 1;
            const int jj = j + dj;
            float v = 0.f;
            if (jj >= 0 && jj < 32) v = xrow[(w + di) * 32 + jj];
            const __nv_bfloat16 h = __float2bfloat16_rn(v);
            Ahi[mbase + (size_t)tap * 128] = h;
            Alo[mbase + (size_t)tap * 128] =
                __float2bfloat16_rn(v - __bfloat162float(h));
        }
    }
}

// ---------------------------------------------------------------------------
// LayerNorm over D=256 -> bf16 hi/lo. Optional addsrc.
// ---------------------------------------------------------------------------
__global__ __launch_bounds__(256) void ln_kernel(
    const float* __restrict__ X, const float* __restrict__ addsrc,
    const float* __restrict__ g, const float* __restrict__ b,
    __nv_bfloat16* __restrict__ oh, __nv_bfloat16* __restrict__ ol)
{
    const size_t row = blockIdx.x;
    const int tid = threadIdx.x;
    __shared__ float red[8];

    float v = X[row * D_MOD + tid];
    if (addsrc) v += addsrc[row * D_MOD + tid];

    float s = v;
#pragma unroll
    for (int o = 16; o; o >>= 1) s += __shfl_xor_sync(0xffffffffu, s, o);
    if ((tid & 31) == 0) red[tid >> 5] = s;
    __syncthreads();
    float mean = 0.f;
#pragma unroll
    for (int i = 0; i < 8; i++) mean += red[i];
    mean *= (1.f / 256.f);
    __syncthreads();

    const float dev = v - mean;
    float q = dev * dev;
#pragma unroll
    for (int o = 16; o; o >>= 1) q += __shfl_xor_sync(0xffffffffu, q, o);
    if ((tid & 31) == 0) red[tid >> 5] = q;
    __syncthreads();
    float var = 0.f;
#pragma unroll
    for (int i = 0; i < 8; i++) var += red[i];
    var *= (1.f / 256.f);

    const float r = dev * rsqrtf(var + 1e-5f) * g[tid] + b[tid];
    const __nv_bfloat16 h = __float2bfloat16_rn(r);
    oh[row * D_MOD + tid] = h;
    ol[row * D_MOD + tid] = __float2bfloat16_rn(r - __bfloat162float(h));
}

// ---------------------------------------------------------------------------
// Fused attention (ba-major rows); writes bf16 hi/lo directly.
// ---------------------------------------------------------------------------
#define ATT_SMEM_FLOATS (25600 + 25600 + 256 + 800 + 800 + 64 + 64 + 8 + 8 + 8)
#define ATT_SMEM_BYTES  (ATT_SMEM_FLOATS * 4)

__global__ __launch_bounds__(256) void attn_kernel(
    const float* __restrict__ qkv,
    __nv_bfloat16* __restrict__ outh, __nv_bfloat16* __restrict__ outl,
    const float* __restrict__ Wl, const float* __restrict__ bl,
    const float* __restrict__ Ww, const float* __restrict__ bw,
    const float* __restrict__ lamb)
{
    extern __shared__ float smf[];
    float* Ks   = smf;
    float* Vs   = Ks + 25600;
    float* qs   = Vs + 25600;
    float* sraw = qs + 256;
    float* satt = sraw + 800;
    float* swl  = satt + 800;
    float* sww  = swl + 64;
    float* sbl  = sww + 64;
    float* sbw  = sbl + 8;
    float* slam = sbw + 8;

    const int tid = threadIdx.x;
    const int bq = blockIdx.x;
    const float scale = 0.17677669529663687f;

    if (tid < 64) { swl[tid] = Wl[tid]; sww[tid] = Ww[tid]; }
    if (tid < 8)  { sbl[tid] = bl[tid]; sbw[tid] = bw[tid]; slam[tid] = lamb[tid]; }

    for (int idx = tid; idx < 25600; idx += 256) {
        const int m = idx >> 8, cc = idx & 255;
        const size_t rowb = ((size_t)m * PIX + bq) * QKV_N;
        Ks[idx] = qkv[rowb + 256 + cc];
        Vs[idx] = qkv[rowb + 512 + cc];
    }
    __syncthreads();

    const int g = tid >> 5, lane = tid & 31;

    for (int n = 0; n < BA; n++) {
        qs[tid] = qkv[((size_t)n * PIX + bq) * QKV_N + tid] * scale;
        __syncthreads();

        for (int e = tid; e < 800; e += 256) {
            const int h = e / 100, m = e - h * 100;
            const float* kp = Ks + m * 256 + h * 32;
            const float* qp = qs + h * 32;
            float d = 0.f;
#pragma unroll
            for (int dd = 0; dd < 32; dd++) d += qp[dd] * kp[dd];
            sraw[e] = d;
        }
        __syncthreads();

        for (int e = tid; e < 800; e += 256) {
            const int gg = e / 100, m = e - gg * 100;
            float s = sbl[gg];
#pragma unroll
            for (int h = 0; h < 8; h++) s += sraw[h * 100 + m] * swl[gg * 8 + h];
            satt[e] = s;
        }
        __syncthreads();

        {
            float mx = -1e30f;
            for (int m = lane; m < 100; m += 32) mx = fmaxf(mx, satt[g * 100 + m]);
#pragma unroll
            for (int o = 16; o; o >>= 1) mx = fmaxf(mx, __shfl_xor_sync(0xffffffffu, mx, o));
            float sum = 0.f;
            for (int m = lane; m < 100; m += 32) {
                const float e2 = __expf(satt[g * 100 + m] - mx);
                sraw[g * 100 + m] = e2;
                sum += e2;
            }
#pragma unroll
            for (int o = 16; o; o >>= 1) sum += __shfl_xor_sync(0xffffffffu, sum, o);
            const float inv = 1.f / sum;
            for (int m = lane; m < 100; m += 32) sraw[g * 100 + m] *= inv;
        }
        __syncthreads();

        for (int e = tid; e < 800; e += 256) {
            const int gg = e / 100, m = e - gg * 100;
            float s = sbw[gg];
#pragma unroll
            for (int h = 0; h < 8; h++) s += sraw[h * 100 + m] * sww[gg * 8 + h];
            s = 0.01f + (s - 0.01f) * (1.f + slam[gg]);
            satt[e] = s;
        }
        __syncthreads();

        {
            const int d = lane;
            float o = 0.f;
            const float* vp = Vs + g * 32 + d;
            const float* ap = satt + g * 100;
#pragma unroll 4
            for (int m = 0; m < 100; m++) o += ap[m] * vp[m * 256];
            const size_t oi = ((size_t)n * PIX + bq) * D_MOD + g * 32 + d;
            const __nv_bfloat16 h = __float2bfloat16_rn(o);
            outh[oi] = h;
            outl[oi] = __float2bfloat16_rn(o - __bfloat162float(h));
        }
        __syncthreads();
    }
}

// ---------------------------------------------------------------------------
extern "C" void kernel_launch(void* const* d_in, const int* in_sizes, int n_in,
                              void* d_out, int out_size)
{
    const float* buffer  = (const float*)d_in[0];
    const float* spa_pos = (const float*)d_in[1];
    const float* W_mlp   = (const float*)d_in[2];
    const float* g1      = (const float*)d_in[3];
    const float* b1      = (const float*)d_in[4];
    const float* Wqkv    = (const float*)d_in[5];
    const float* Wproj   = (const float*)d_in[6];
    const float* bproj   = (const float*)d_in[7];
    const float* Wl      = (const float*)d_in[8];
    const float* bl      = (const float*)d_in[9];
    const float* Ww      = (const float*)d_in[10];
    const float* bw      = (const float*)d_in[11];
    const float* lamb    = (const float*)d_in[12];
    const float* g2      = (const float*)d_in[13];
    const float* b2      = (const float*)d_in[14];
    const float* W1      = (const float*)d_in[15];
    const float* W2      = (const float*)d_in[16];
    const float* Wconv   = (const float*)d_in[17];
    float* out = (float*)d_out;

    float *T, *PE, *QKV, *S2;
    cudaGetSymbolAddress((void**)&T,   g_T);
    cudaGetSymbolAddress((void**)&PE,  g_PE);
    cudaGetSymbolAddress((void**)&QKV, g_QKV);
    cudaGetSymbolAddress((void**)&S2,  g_S2);

    __nv_bfloat16 *Ah, *Al, *Xh, *Xl, *AOh, *AOl, *Yh, *Yl, *Fh, *Fl;
    __nv_bfloat16 *Wmh, *Wml, *Wqh, *Wql, *Wph, *Wpl, *W1h, *W1l, *W2h, *W2l, *Wch, *Wcl;
    cudaGetSymbolAddress((void**)&Ah,  gA_hi);   cudaGetSymbolAddress((void**)&Al,  gA_lo);
    cudaGetSymbolAddress((void**)&Xh,  gX_hi);   cudaGetSymbolAddress((void**)&Xl,  gX_lo);
    cudaGetSymbolAddress((void**)&AOh, gAO_hi);  cudaGetSymbolAddress((void**)&AOl, gAO_lo);
    cudaGetSymbolAddress((void**)&Yh,  gY_hi);   cudaGetSymbolAddress((void**)&Yl,  gY_lo);
    cudaGetSymbolAddress((void**)&Fh,  gF_hi);   cudaGetSymbolAddress((void**)&Fl,  gF_lo);
    cudaGetSymbolAddress((void**)&Wmh, gWmlp_hi);  cudaGetSymbolAddress((void**)&Wml, gWmlp_lo);
    cudaGetSymbolAddress((void**)&Wqh, gWqkv_hi);  cudaGetSymbolAddress((void**)&Wql, gWqkv_lo);
    cudaGetSymbolAddress((void**)&Wph, gWproj_hi); cudaGetSymbolAddress((void**)&Wpl, gWproj_lo);
    cudaGetSymbolAddress((void**)&W1h, gW1_hi);    cudaGetSymbolAddress((void**)&W1l, gW1_lo);
    cudaGetSymbolAddress((void**)&W2h, gW2_hi);    cudaGetSymbolAddress((void**)&W2l, gW2_lo);
    cudaGetSymbolAddress((void**)&Wch, gWc_hi);    cudaGetSymbolAddress((void**)&Wcl, gWc_lo);

    cudaFuncSetAttribute(attn_kernel, cudaFuncAttributeMaxDynamicSharedMemorySize,
                         ATT_SMEM_BYTES);
    cudaFuncSetAttribute(gemm_mma, cudaFuncAttributeMaxDynamicSharedMemorySize,
                         GSM_TOTAL);

    // App launch #4 is what ncu captures (2 harness kernels + -s 5).
    // 1
    im2col2<<<dim3(4, 4, BA), 256>>>(buffer, Ah, Al);
    // 2
    wsplit_mlp<<<(KIN * D_MOD + 255) / 256, 256>>>(W_mlp, Wmh, Wml);
    // 3
    wsplit_kernel<<<(D_MOD * QKV_N + 255) / 256, 256>>>(Wqkv, D_MOD, QKV_N, Wqh, Wql);
    // 4  <-- ncu capture target: conv GEMM
    gemm_mma<<<dim3(D_MOD / 64, TOK_M / 128), 256, GSM_TOTAL>>>(
        Ah, Al, Wmh, Wml, T, TOK_M, D_MOD, KIN,
        nullptr, nullptr, 0, nullptr, nullptr, nullptr);
    // 5-6: PE conv
    im2col2<<<dim3(4, 4, BA), 256>>>(spa_pos, Ah, Al);
    gemm_mma<<<dim3(D_MOD / 64, TOK_M / 128), 256, GSM_TOTAL>>>(
        Ah, Al, Wmh, Wml, PE, TOK_M, D_MOD, KIN,
        nullptr, nullptr, 0, nullptr, nullptr, nullptr);
    // remaining weight splits
    wsplit_kernel<<<(D_MOD * D_MOD + 255) / 256, 256>>>(Wproj, D_MOD, D_MOD, Wph, Wpl);
    wsplit_kernel<<<(D_MOD * D_FF + 255) / 256, 256>>>(W1, D_MOD, D_FF, W1h, W1l);
    wsplit_kernel<<<(D_FF * D_MOD + 255) / 256, 256>>>(W2, D_FF, D_MOD, W2h, W2l);
    split_kernel<<<(CCH * D_MOD + 255) / 256, 256>>>(Wconv, (size_t)CCH * D_MOD, Wch, Wcl);

    // x = LN(T + PE) -> hi/lo
    ln_kernel<<<TOK_M, 256>>>(T, PE, g1, b1, Xh, Xl);

    // qkv
    gemm_mma<<<dim3(QKV_N / 64, TOK_M / 128), 256, GSM_TOTAL>>>(
        Xh, Xl, Wqh, Wql, QKV, TOK_M, QKV_N, D_MOD,
        nullptr, nullptr, 0, nullptr, nullptr, nullptr);

    // attention -> AO hi/lo
    attn_kernel<<<PIX, 256, ATT_SMEM_BYTES>>>(QKV, AOh, AOl, Wl, bl, Ww, bw, lamb);

    // proj: S2 = AO @ Wproj + bproj + T  (fp32)
    gemm_mma<<<dim3(D_MOD / 64, TOK_M / 128), 256, GSM_TOTAL>>>(
        AOh, AOl, Wph, Wpl, S2, TOK_M, D_MOD, D_MOD,
        bproj, T, 0, nullptr, nullptr, nullptr);

    // y = LN(S2) -> hi/lo
    ln_kernel<<<TOK_M, 256>>>(S2, nullptr, g2, b2, Yh, Yl);

    // FF1: relu(y@W1) -> hi/lo
    gemm_mma<<<dim3(D_FF / 64, TOK_M / 128), 256, GSM_TOTAL>>>(
        Yh, Yl, W1h, W1l, nullptr, TOK_M, D_FF, D_MOD,
        nullptr, nullptr, 1, Fh, Fl, nullptr);
    // FF2: XF = FF1@W2 + S2 -> hi/lo (reuse X buffers)
    gemm_mma<<<dim3(D_MOD / 64, TOK_M / 128), 256, GSM_TOTAL>>>(
        Fh, Fl, W2h, W2l, nullptr, TOK_M, D_MOD, D_FF,
        nullptr, S2, 0, Xh, Xl, nullptr);

    // Token2SAI + 1x1x1 conv as GEMM with scatter epilogue -> out
    gemm_mma<<<dim3(CCH / 64, TOK_M / 128), 256, GSM_TOTAL>>>(
        Xh, Xl, Wch, Wcl, nullptr, TOK_M, CCH, D_MOD,
        nullptr, nullptr, 0, nullptr, nullptr, out);
}

// round 9
// speedup vs baseline: 2.2420x; 1.5038x over previous
#include <cuda_runtime.h>
#include <cuda_bf16.h>
#include <stdint.h>
#include <math.h>

// ---------------------------------------------------------------------------
// Problem constants: b=4, c=128, a=25, h=w=32
// Token order: m = ba*1024 + p (ba-major). Conv K order: k = tap*128 + c.
// ---------------------------------------------------------------------------
#define TOK_M   102400
#define D_MOD   256
#define D_FF    512
#define QKV_N   768
#define BA      100
#define PIX     1024
#define CCH     128
#define AA      25
#define KIN     1152

// ------------------------- scratch (static device) -------------------------
__device__ float g_T  [TOK_M * D_MOD];
__device__ float g_PE [TOK_M * D_MOD];
__device__ float g_QKV[TOK_M * QKV_N];
__device__ float g_S2 [TOK_M * D_MOD];

__device__ __nv_bfloat16 gA_hi[(size_t)TOK_M * KIN];
__device__ __nv_bfloat16 gA_lo[(size_t)TOK_M * KIN];
__device__ __nv_bfloat16 gX_hi[TOK_M * D_MOD],  gX_lo[TOK_M * D_MOD];
__device__ __nv_bfloat16 gAO_hi[TOK_M * D_MOD], gAO_lo[TOK_M * D_MOD];
__device__ __nv_bfloat16 gY_hi[TOK_M * D_MOD],  gY_lo[TOK_M * D_MOD];
__device__ __nv_bfloat16 gF_hi[TOK_M * D_FF],   gF_lo[TOK_M * D_FF];

__device__ __nv_bfloat16 gWmlp_hi [D_MOD * KIN],   gWmlp_lo [D_MOD * KIN];
__device__ __nv_bfloat16 gWqkv_hi [QKV_N * D_MOD], gWqkv_lo [QKV_N * D_MOD];
__device__ __nv_bfloat16 gWproj_hi[D_MOD * D_MOD], gWproj_lo[D_MOD * D_MOD];
__device__ __nv_bfloat16 gW1_hi   [D_FF * D_MOD],  gW1_lo   [D_FF * D_MOD];
__device__ __nv_bfloat16 gW2_hi   [D_MOD * D_FF],  gW2_lo   [D_MOD * D_FF];
__device__ __nv_bfloat16 gWc_hi   [CCH * D_MOD],   gWc_lo   [CCH * D_MOD];

// ---------------------------------------------------------------------------
// base-target-legal PTX helpers (sm_80+)
// ---------------------------------------------------------------------------
__device__ __forceinline__ uint32_t smem_u32(const void* p) {
    uint32_t a;
    asm("{ .reg .u64 t; cvta.to.shared.u64 t, %1; cvt.u32.u64 %0, t; }"
        : "=r"(a) : "l"(p));
    return a;
}
__device__ __forceinline__ void ldsm_x4(uint32_t* r, uint32_t addr) {
    asm volatile("ldmatrix.sync.aligned.m8n8.x4.shared.b16 {%0,%1,%2,%3}, [%4];"
        : "=r"(r[0]), "=r"(r[1]), "=r"(r[2]), "=r"(r[3]) : "r"(addr));
}
__device__ __forceinline__ void mma16816(float* c, const uint32_t* a, const uint32_t* b) {
    asm volatile(
        "mma.sync.aligned.m16n8k16.row.col.f32.bf16.bf16.f32 "
        "{%0,%1,%2,%3}, {%4,%5,%6,%7}, {%8,%9}, {%0,%1,%2,%3};"
        : "+f"(c[0]), "+f"(c[1]), "+f"(c[2]), "+f"(c[3])
        : "r"(a[0]), "r"(a[1]), "r"(a[2]), "r"(a[3]), "r"(b[0]), "r"(b[1]));
}
#define CP16(dst, src) \
    asm volatile("cp.async.cg.shared.global [%0], [%1], 16;" \
        :: "r"(dst), "l"(src) : "memory")
#define CP_COMMIT() asm volatile("cp.async.commit_group;" ::: "memory")
#define CP_WAIT0()  asm volatile("cp.async.wait_group 0;" ::: "memory")
#define CP_WAIT1()  asm volatile("cp.async.wait_group 1;" ::: "memory")

// ---------------------------------------------------------------------------
// bf16x3 HMMA GEMM. BM=128, BN=64, BK=32; 8 warps (4m x 2n), warp 32x32.
// 3-stage cp.async pipeline; B fragments via merged ldmatrix.x4
// (lane quadrants = (n-subtile, k-half)) -> 128 LDSM vs 384 HMMA per chunk.
// ---------------------------------------------------------------------------
#define RS 40
#define SM_AH 0
#define SM_AL 10240
#define SM_BH 20480
#define SM_BL 25600
#define SM_BUF 30720
#define GSM_TOTAL (3 * SM_BUF)

__global__ __launch_bounds__(256) void gemm_mma(
    const __nv_bfloat16* __restrict__ Ahi, const __nv_bfloat16* __restrict__ Alo,
    const __nv_bfloat16* __restrict__ Bhi, const __nv_bfloat16* __restrict__ Blo,
    float* __restrict__ C, int M, int N, int K,
    const float* __restrict__ bias, const float* __restrict__ resid, int relu,
    __nv_bfloat16* __restrict__ Ohi, __nv_bfloat16* __restrict__ Olo,
    float* __restrict__ sai)
{
    extern __shared__ char sm[];
    const uint32_t smb = smem_u32(sm);
    const int tid = threadIdx.x;
    const int lane = tid & 31;
    const int wid = tid >> 5;
    const int warpm = wid & 3;
    const int warpn = wid >> 2;
    const int m0 = blockIdx.y * 128;
    const int n0 = blockIdx.x * 64;

    const int arow = tid >> 1;
    const int aseg = tid & 1;
    const uint32_t a_sm_off = (uint32_t)arow * (RS * 2) + aseg * 32;
    const __nv_bfloat16* pAh = Ahi + (size_t)(m0 + arow) * K + aseg * 16;
    const __nv_bfloat16* pAl = Alo + (size_t)(m0 + arow) * K + aseg * 16;

    const int bt   = tid & 127;
    const int brow = bt >> 1;
    const int bseg = bt & 1;
    const uint32_t b_sm_off = (uint32_t)brow * (RS * 2) + bseg * 32;
    const int is_blo = (tid >= 128);
    const __nv_bfloat16* pB =
        (is_blo ? Blo : Bhi) + (size_t)(n0 + brow) * K + bseg * 16;
    const uint32_t b_sm_base = is_blo ? SM_BL : SM_BH;

    const int nch = K >> 5;

#pragma unroll
    for (int pt = 0; pt < 2; pt++) {
        const uint32_t stg = (uint32_t)pt * SM_BUF;
        const size_t kc = (size_t)pt * 32;
        CP16(smb + stg + SM_AH + a_sm_off,      pAh + kc);
        CP16(smb + stg + SM_AH + a_sm_off + 16, pAh + kc + 8);
        CP16(smb + stg + SM_AL + a_sm_off,      pAl + kc);
        CP16(smb + stg + SM_AL + a_sm_off + 16, pAl + kc + 8);
        CP16(smb + stg + b_sm_base + b_sm_off,      pB + kc);
        CP16(smb + stg + b_sm_base + b_sm_off + 16, pB + kc + 8);
        CP_COMMIT();
    }

    float acc[2][4][4];
#pragma unroll
    for (int im = 0; im < 2; im++)
#pragma unroll
        for (int in = 0; in < 4; in++)
#pragma unroll
            for (int r = 0; r < 4; r++) acc[im][in][r] = 0.f;

    const uint32_t a_ld_row = (uint32_t)(warpm * 32 + (lane & 15));
    const uint32_t a_ld_k8  = (uint32_t)((lane >> 4) * 8);
    // B x4 lane mapping: group = lane>>3: (nsub, khalf) = (group>>1, group&1)
    const uint32_t b_ld_row = (uint32_t)(warpn * 32 + ((lane >> 4) & 1) * 8 + (lane & 7));
    const uint32_t b_ld_k8  = (uint32_t)(((lane >> 3) & 1) * 8);

    int sc = 0;
    for (int t = 0; t < nch; t++) {
        if (t + 1 < nch) { CP_WAIT1(); } else { CP_WAIT0(); }
        __syncthreads();

        if (t + 2 < nch) {
            const int si = (sc >= 1) ? sc - 1 : 2;
            const uint32_t stg = (uint32_t)si * SM_BUF;
            const size_t kc = (size_t)(t + 2) * 32;
            CP16(smb + stg + SM_AH + a_sm_off,      pAh + kc);
            CP16(smb + stg + SM_AH + a_sm_off + 16, pAh + kc + 8);
            CP16(smb + stg + SM_AL + a_sm_off,      pAl + kc);
            CP16(smb + stg + SM_AL + a_sm_off + 16, pAl + kc + 8);
            CP16(smb + stg + b_sm_base + b_sm_off,      pB + kc);
            CP16(smb + stg + b_sm_base + b_sm_off + 16, pB + kc + 8);
            CP_COMMIT();
        }

        const uint32_t cur = (uint32_t)sc * SM_BUF;
#pragma unroll
        for (int ks = 0; ks < 2; ks++) {
            uint32_t ah[2][4], al[2][4], bh[4][2], bl[4][2];
#pragma unroll
            for (int im = 0; im < 2; im++) {
                const uint32_t ao = cur +
                    ((a_ld_row + im * 16) * RS + ks * 16 + a_ld_k8) * 2;
                ldsm_x4(ah[im], smb + SM_AH + ao);
                ldsm_x4(al[im], smb + SM_AL + ao);
            }
#pragma unroll
            for (int p = 0; p < 2; p++) {
                const uint32_t bo = cur +
                    ((b_ld_row + p * 16) * RS + ks * 16 + b_ld_k8) * 2;
                uint32_t r[4];
                ldsm_x4(r, smb + SM_BH + bo);
                bh[2*p][0] = r[0]; bh[2*p][1] = r[1];
                bh[2*p+1][0] = r[2]; bh[2*p+1][1] = r[3];
                ldsm_x4(r, smb + SM_BL + bo);
                bl[2*p][0] = r[0]; bl[2*p][1] = r[1];
                bl[2*p+1][0] = r[2]; bl[2*p+1][1] = r[3];
            }
#pragma unroll
            for (int im = 0; im < 2; im++)
#pragma unroll
                for (int in = 0; in < 4; in++) {
                    mma16816(acc[im][in], ah[im], bh[in]);
                    mma16816(acc[im][in], ah[im], bl[in]);
                    mma16816(acc[im][in], al[im], bh[in]);
                }
        }
        sc = (sc >= 2) ? 0 : sc + 1;
    }

    // ---- epilogue ----
#pragma unroll
    for (int im = 0; im < 2; im++) {
#pragma unroll
        for (int in = 0; in < 4; in++) {
            const int mrow = m0 + warpm * 32 + im * 16 + (lane >> 2);
            const int ncol = n0 + warpn * 32 + in * 8 + (lane & 3) * 2;
#pragma unroll
            for (int r = 0; r < 2; r++) {
                const int m = mrow + r * 8;
                float v0 = acc[im][in][r * 2 + 0];
                float v1 = acc[im][in][r * 2 + 1];
                if (bias)  { v0 += bias[ncol]; v1 += bias[ncol + 1]; }
                if (relu)  { v0 = fmaxf(v0, 0.f); v1 = fmaxf(v1, 0.f); }
                if (resid) {
                    const float* rp = resid + (size_t)m * N + ncol;
                    v0 += rp[0]; v1 += rp[1];
                }
                if (C) {
                    float2 f2; f2.x = v0; f2.y = v1;
                    *(float2*)(C + (size_t)m * N + ncol) = f2;
                }
                if (Ohi) {
                    __nv_bfloat16 h0 = __float2bfloat16_rn(v0);
                    __nv_bfloat16 h1 = __float2bfloat16_rn(v1);
                    __nv_bfloat162 hv; hv.x = h0; hv.y = h1;
                    __nv_bfloat162 lv;
                    lv.x = __float2bfloat16_rn(v0 - __bfloat162float(h0));
                    lv.y = __float2bfloat16_rn(v1 - __bfloat162float(h1));
                    *(__nv_bfloat162*)(Ohi + (size_t)m * N + ncol) = hv;
                    *(__nv_bfloat162*)(Olo + (size_t)m * N + ncol) = lv;
                }
                if (sai) {
                    const int ba = m >> 10, p = m & 1023;
                    const int b_ = ba / AA, a_ = ba - b_ * AA;
                    sai[((size_t)(b_ * CCH + ncol)     * AA + a_) * PIX + p] = v0;
                    sai[((size_t)(b_ * CCH + ncol + 1) * AA + a_) * PIX + p] = v1;
                }
            }
        }
    }
}

// ---------------------------------------------------------------------------
// weight transpose + split kernels
// ---------------------------------------------------------------------------
__global__ void wsplit_kernel(const float* __restrict__ W, int K, int N,
                              __nv_bfloat16* __restrict__ oh,
                              __nv_bfloat16* __restrict__ ol)
{
    const int idx = blockIdx.x * 256 + threadIdx.x;
    if (idx >= K * N) return;
    const int k = idx / N, n = idx - k * N;
    const float v = W[idx];
    const __nv_bfloat16 h = __float2bfloat16_rn(v);
    oh[(size_t)n * K + k] = h;
    ol[(size_t)n * K + k] = __float2bfloat16_rn(v - __bfloat162float(h));
}

__global__ void wsplit_mlp(const float* __restrict__ W,
                           __nv_bfloat16* __restrict__ oh,
                           __nv_bfloat16* __restrict__ ol)
{
    const int idx = blockIdx.x * 256 + threadIdx.x;
    if (idx >= KIN * D_MOD) return;
    const int kk = idx / D_MOD, n = idx - kk * D_MOD;
    const int c = kk / 9, tap = kk - c * 9;
    const int kp = tap * 128 + c;
    const float v = W[idx];
    const __nv_bfloat16 h = __float2bfloat16_rn(v);
    oh[(size_t)n * KIN + kp] = h;
    ol[(size_t)n * KIN + kp] = __float2bfloat16_rn(v - __bfloat162float(h));
}

__global__ void split_kernel(const float* __restrict__ X, size_t n,
                             __nv_bfloat16* __restrict__ oh,
                             __nv_bfloat16* __restrict__ ol)
{
    const size_t i = (size_t)blockIdx.x * 256 + threadIdx.x;
    if (i >= n) return;
    const float v = X[i];
    const __nv_bfloat16 h = __float2bfloat16_rn(v);
    oh[i] = h;
    ol[i] = __float2bfloat16_rn(v - __bfloat162float(h));
}

// ---------------------------------------------------------------------------
// im2col (coalesced): A[m = ba*1024+p][k = tap*128+c] bf16 hi/lo.
// ---------------------------------------------------------------------------
__global__ __launch_bounds__(256) void im2col2(
    const float* __restrict__ src,
    __nv_bfloat16* __restrict__ Ahi, __nv_bfloat16* __restrict__ Alo)
{
    __shared__ float xs[32 * 321];
    const int tid = threadIdx.x;
    const int i0 = blockIdx.x * 8;
    const int c0 = blockIdx.y * 32;
    const int ba = blockIdx.z;
    const int b_ = ba / AA, a_ = ba - b_ * AA;

    for (int l = tid; l < 10240; l += 256) {
        const int c = l / 320;
        const int rem = l - c * 320;
        const int r = rem >> 5, col = rem & 31;
        const int ii = i0 - 1 + r;
        float v = 0.f;
        if (ii >= 0 && ii < 32)
            v = src[(((size_t)(b_ * CCH + c0 + c)) * AA + a_) * PIX + ii * 32 + col];
        xs[c * 321 + rem] = v;
    }
    __syncthreads();

    const int w = tid >> 5, lane = tid & 31;
    const int i = i0 + w;
    const float* xrow = xs + lane * 321;
    for (int j = 0; j < 32; j++) {
        const size_t m = (size_t)ba * PIX + i * 32 + j;
        const size_t mbase = m * KIN + c0 + lane;
#pragma unroll
        for (int tap = 0; tap < 9; tap++) {
            const int di = tap / 3, dj = tap - di * 3 - 1;
            const int jj = j + dj;
            float v = 0.f;
            if (jj >= 0 && jj < 32) v = xrow[(w + di) * 32 + jj];
            const __nv_bfloat16 h = __float2bfloat16_rn(v);
            Ahi[mbase + (size_t)tap * 128] = h;
            Alo[mbase + (size_t)tap * 128] =
                __float2bfloat16_rn(v - __bfloat162float(h));
        }
    }
}

// ---------------------------------------------------------------------------
// LayerNorm over D=256 -> bf16 hi/lo. Optional addsrc.
// ---------------------------------------------------------------------------
__global__ __launch_bounds__(256) void ln_kernel(
    const float* __restrict__ X, const float* __restrict__ addsrc,
    const float* __restrict__ g, const float* __restrict__ b,
    __nv_bfloat16* __restrict__ oh, __nv_bfloat16* __restrict__ ol)
{
    const size_t row = blockIdx.x;
    const int tid = threadIdx.x;
    __shared__ float red[8];

    float v = X[row * D_MOD + tid];
    if (addsrc) v += addsrc[row * D_MOD + tid];

    float s = v;
#pragma unroll
    for (int o = 16; o; o >>= 1) s += __shfl_xor_sync(0xffffffffu, s, o);
    if ((tid & 31) == 0) red[tid >> 5] = s;
    __syncthreads();
    float mean = 0.f;
#pragma unroll
    for (int i = 0; i < 8; i++) mean += red[i];
    mean *= (1.f / 256.f);
    __syncthreads();

    const float dev = v - mean;
    float q = dev * dev;
#pragma unroll
    for (int o = 16; o; o >>= 1) q += __shfl_xor_sync(0xffffffffu, q, o);
    if ((tid & 31) == 0) red[tid >> 5] = q;
    __syncthreads();
    float var = 0.f;
#pragma unroll
    for (int i = 0; i < 8; i++) var += red[i];
    var *= (1.f / 256.f);

    const float r = dev * rsqrtf(var + 1e-5f) * g[tid] + b[tid];
    const __nv_bfloat16 h = __float2bfloat16_rn(r);
    oh[row * D_MOD + tid] = h;
    ol[row * D_MOD + tid] = __float2bfloat16_rn(r - __bfloat162float(h));
}

// ---------------------------------------------------------------------------
// Fused attention v2 — conflict-free smem.
// Kt[cc][m] pad 105 (odd -> conflict-free), Vs[m][cc]. Warp g owns head g.
// Tail-quarter reads (m=96..99) are full-warp and masked AFTER the load,
// so sraw/satt need tail padding inside the allocation (TAILPAD).
// ---------------------------------------------------------------------------
#define KTP 105
#define TAILPAD 64
#define ATT_SMEM_FLOATS (256 * KTP + 25600 + 256 + 800 + 800 + TAILPAD)
#define ATT_SMEM_BYTES  (ATT_SMEM_FLOATS * 4)

__global__ __launch_bounds__(256) void attn_kernel(
    const float* __restrict__ qkv,
    __nv_bfloat16* __restrict__ outh, __nv_bfloat16* __restrict__ outl,
    const float* __restrict__ Wl, const float* __restrict__ bl,
    const float* __restrict__ Ww, const float* __restrict__ bw,
    const float* __restrict__ lamb)
{
    extern __shared__ float smf[];
    float* Kt   = smf;                 // [256][105]
    float* Vs   = Kt + 256 * KTP;      // [100][256]
    float* qs   = Vs + 25600;          // [256]
    float* sraw = qs + 256;            // [8][100]
    float* satt = sraw + 800;          // [8][100] + tail pad

    const int tid = threadIdx.x;
    const int g = tid >> 5, lane = tid & 31;
    const int bq = blockIdx.x;
    const float scale = 0.17677669529663687f;

    float wl[8], ww[8];
#pragma unroll
    for (int h = 0; h < 8; h++) { wl[h] = Wl[g * 8 + h]; ww[h] = Ww[g * 8 + h]; }
    const float blg = bl[g], bwg = bw[g];
    const float lam = 1.f + lamb[g];

    for (int idx = tid; idx < 25600; idx += 256) {
        const int m = idx >> 8, cc = idx & 255;
        const size_t rowb = ((size_t)m * PIX + bq) * QKV_N;
        Kt[cc * KTP + m] = qkv[rowb + 256 + cc];
        Vs[idx]          = qkv[rowb + 512 + cc];
    }
    __syncthreads();

    for (int n = 0; n < BA; n++) {
        qs[tid] = qkv[((size_t)n * PIX + bq) * QKV_N + tid] * scale;
        __syncthreads();                       // sync A

        // ---- scores (head g): sraw[g][m] = q_g . k_{g,m}
        const float qreg = qs[tid];
        float a0 = 0.f, a1 = 0.f, a2 = 0.f, a3 = 0.f;
        const float* kb = Kt + (g * 32) * KTP;
#pragma unroll
        for (int dd = 0; dd < 32; dd++) {
            const float qd = __shfl_sync(0xffffffffu, qreg, dd);
            const float* kr = kb + dd * KTP;
            a0 += qd * kr[lane];
            a1 += qd * kr[32 + lane];
            a2 += qd * kr[64 + lane];
            a3 += qd * kr[96 + lane];          // lanes>=4 read into Vs (masked)
        }
        sraw[g * 100 + lane]      = a0;
        sraw[g * 100 + 32 + lane] = a1;
        sraw[g * 100 + 64 + lane] = a2;
        if (lane < 4) sraw[g * 100 + 96 + lane] = a3;
        __syncthreads();                       // sync B

        // ---- talking-heads pre-mix + softmax (row g)
        float s0 = blg, s1 = blg, s2 = blg, s3 = blg;
#pragma unroll
        for (int h = 0; h < 8; h++) {
            const float* sr = sraw + h * 100;
            const float w = wl[h];
            s0 += w * sr[lane];
            s1 += w * sr[32 + lane];
            s2 += w * sr[64 + lane];
            s3 += w * sr[96 + lane];           // garbage for lane>=4, masked
        }
        if (lane >= 4) s3 = -1e30f;
        float mx = fmaxf(fmaxf(s0, s1), fmaxf(s2, s3));
#pragma unroll
        for (int o = 16; o; o >>= 1) mx = fmaxf(mx, __shfl_xor_sync(0xffffffffu, mx, o));
        float e0 = __expf(s0 - mx);
        float e1 = __expf(s1 - mx);
        float e2 = __expf(s2 - mx);
        float e3 = (lane < 4) ? __expf(s3 - mx) : 0.f;
        float sum = e0 + e1 + e2 + e3;
#pragma unroll
        for (int o = 16; o; o >>= 1) sum += __shfl_xor_sync(0xffffffffu, sum, o);
        const float inv = 1.f / sum;
        satt[g * 100 + lane]      = e0 * inv;
        satt[g * 100 + 32 + lane] = e1 * inv;
        satt[g * 100 + 64 + lane] = e2 * inv;
        if (lane < 4) satt[g * 100 + 96 + lane] = e3 * inv;
        __syncthreads();                       // sync C

        // ---- post-mix + attnscale (in registers)
        float w0 = bwg, w1 = bwg, w2 = bwg, w3 = bwg;
#pragma unroll
        for (int h = 0; h < 8; h++) {
            const float* sa = satt + h * 100;
            const float w = ww[h];
            w0 += w * sa[lane];
            w1 += w * sa[32 + lane];
            w2 += w * sa[64 + lane];
            w3 += w * sa[96 + lane];           // in-bounds via TAILPAD, masked
        }
        w0 = 0.01f + (w0 - 0.01f) * lam;
        w1 = 0.01f + (w1 - 0.01f) * lam;
        w2 = 0.01f + (w2 - 0.01f) * lam;
        w3 = 0.01f + (w3 - 0.01f) * lam;

        // ---- AV: out[g][lane] = sum_m w_m * V[m][g*32+lane]
        float o = 0.f;
        const float* vb = Vs + g * 32 + lane;
#pragma unroll 4
        for (int sl = 0; sl < 32; sl++) {
            const float wm0 = __shfl_sync(0xffffffffu, w0, sl);
            const float wm1 = __shfl_sync(0xffffffffu, w1, sl);
            const float wm2 = __shfl_sync(0xffffffffu, w2, sl);
            o += wm0 * vb[sl * 256];
            o += wm1 * vb[(32 + sl) * 256];
            o += wm2 * vb[(64 + sl) * 256];
        }
#pragma unroll
        for (int sl = 0; sl < 4; sl++) {
            const float wm3 = __shfl_sync(0xffffffffu, w3, sl);
            o += wm3 * vb[(96 + sl) * 256];
        }
        const size_t oi = ((size_t)n * PIX + bq) * D_MOD + g * 32 + lane;
        const __nv_bfloat16 h = __float2bfloat16_rn(o);
        outh[oi] = h;
        outl[oi] = __float2bfloat16_rn(o - __bfloat162float(h));
    }
}

// ---------------------------------------------------------------------------
extern "C" void kernel_launch(void* const* d_in, const int* in_sizes, int n_in,
                              void* d_out, int out_size)
{
    const float* buffer  = (const float*)d_in[0];
    const float* spa_pos = (const float*)d_in[1];
    const float* W_mlp   = (const float*)d_in[2];
    const float* g1      = (const float*)d_in[3];
    const float* b1      = (const float*)d_in[4];
    const float* Wqkv    = (const float*)d_in[5];
    const float* Wproj   = (const float*)d_in[6];
    const float* bproj   = (const float*)d_in[7];
    const float* Wl      = (const float*)d_in[8];
    const float* bl      = (const float*)d_in[9];
    const float* Ww      = (const float*)d_in[10];
    const float* bw      = (const float*)d_in[11];
    const float* lamb    = (const float*)d_in[12];
    const float* g2      = (const float*)d_in[13];
    const float* b2      = (const float*)d_in[14];
    const float* W1      = (const float*)d_in[15];
    const float* W2      = (const float*)d_in[16];
    const float* Wconv   = (const float*)d_in[17];
    float* out = (float*)d_out;

    float *T, *PE, *QKV, *S2;
    cudaGetSymbolAddress((void**)&T,   g_T);
    cudaGetSymbolAddress((void**)&PE,  g_PE);
    cudaGetSymbolAddress((void**)&QKV, g_QKV);
    cudaGetSymbolAddress((void**)&S2,  g_S2);

    __nv_bfloat16 *Ah, *Al, *Xh, *Xl, *AOh, *AOl, *Yh, *Yl, *Fh, *Fl;
    __nv_bfloat16 *Wmh, *Wml, *Wqh, *Wql, *Wph, *Wpl, *W1h, *W1l, *W2h, *W2l, *Wch, *Wcl;
    cudaGetSymbolAddress((void**)&Ah,  gA_hi);   cudaGetSymbolAddress((void**)&Al,  gA_lo);
    cudaGetSymbolAddress((void**)&Xh,  gX_hi);   cudaGetSymbolAddress((void**)&Xl,  gX_lo);
    cudaGetSymbolAddress((void**)&AOh, gAO_hi);  cudaGetSymbolAddress((void**)&AOl, gAO_lo);
    cudaGetSymbolAddress((void**)&Yh,  gY_hi);   cudaGetSymbolAddress((void**)&Yl,  gY_lo);
    cudaGetSymbolAddress((void**)&Fh,  gF_hi);   cudaGetSymbolAddress((void**)&Fl,  gF_lo);
    cudaGetSymbolAddress((void**)&Wmh, gWmlp_hi);  cudaGetSymbolAddress((void**)&Wml, gWmlp_lo);
    cudaGetSymbolAddress((void**)&Wqh, gWqkv_hi);  cudaGetSymbolAddress((void**)&Wql, gWqkv_lo);
    cudaGetSymbolAddress((void**)&Wph, gWproj_hi); cudaGetSymbolAddress((void**)&Wpl, gWproj_lo);
    cudaGetSymbolAddress((void**)&W1h, gW1_hi);    cudaGetSymbolAddress((void**)&W1l, gW1_lo);
    cudaGetSymbolAddress((void**)&W2h, gW2_hi);    cudaGetSymbolAddress((void**)&W2l, gW2_lo);
    cudaGetSymbolAddress((void**)&Wch, gWc_hi);    cudaGetSymbolAddress((void**)&Wcl, gWc_lo);

    cudaFuncSetAttribute(attn_kernel, cudaFuncAttributeMaxDynamicSharedMemorySize,
                         ATT_SMEM_BYTES);
    cudaFuncSetAttribute(gemm_mma, cudaFuncAttributeMaxDynamicSharedMemorySize,
                         GSM_TOTAL);

    // App launch #4 = ncu capture target (conv GEMM).
    im2col2<<<dim3(4, 4, BA), 256>>>(buffer, Ah, Al);
    wsplit_mlp<<<(KIN * D_MOD + 255) / 256, 256>>>(W_mlp, Wmh, Wml);
    wsplit_kernel<<<(D_MOD * QKV_N + 255) / 256, 256>>>(Wqkv, D_MOD, QKV_N, Wqh, Wql);
    gemm_mma<<<dim3(D_MOD / 64, TOK_M / 128), 256, GSM_TOTAL>>>(
        Ah, Al, Wmh, Wml, T, TOK_M, D_MOD, KIN,
        nullptr, nullptr, 0, nullptr, nullptr, nullptr);
    im2col2<<<dim3(4, 4, BA), 256>>>(spa_pos, Ah, Al);
    gemm_mma<<<dim3(D_MOD / 64, TOK_M / 128), 256, GSM_TOTAL>>>(
        Ah, Al, Wmh, Wml, PE, TOK_M, D_MOD, KIN,
        nullptr, nullptr, 0, nullptr, nullptr, nullptr);
    wsplit_kernel<<<(D_MOD * D_MOD + 255) / 256, 256>>>(Wproj, D_MOD, D_MOD, Wph, Wpl);
    wsplit_kernel<<<(D_MOD * D_FF + 255) / 256, 256>>>(W1, D_MOD, D_FF, W1h, W1l);
    wsplit_kernel<<<(D_FF * D_MOD + 255) / 256, 256>>>(W2, D_FF, D_MOD, W2h, W2l);
    split_kernel<<<(CCH * D_MOD + 255) / 256, 256>>>(Wconv, (size_t)CCH * D_MOD, Wch, Wcl);

    ln_kernel<<<TOK_M, 256>>>(T, PE, g1, b1, Xh, Xl);

    gemm_mma<<<dim3(QKV_N / 64, TOK_M / 128), 256, GSM_TOTAL>>>(
        Xh, Xl, Wqh, Wql, QKV, TOK_M, QKV_N, D_MOD,
        nullptr, nullptr, 0, nullptr, nullptr, nullptr);

    attn_kernel<<<PIX, 256, ATT_SMEM_BYTES>>>(QKV, AOh, AOl, Wl, bl, Ww, bw, lamb);

    gemm_mma<<<dim3(D_MOD / 64, TOK_M / 128), 256, GSM_TOTAL>>>(
        AOh, AOl, Wph, Wpl, S2, TOK_M, D_MOD, D_MOD,
        bproj, T, 0, nullptr, nullptr, nullptr);

    ln_kernel<<<TOK_M, 256>>>(S2, nullptr, g2, b2, Yh, Yl);

    gemm_mma<<<dim3(D_FF / 64, TOK_M / 128), 256, GSM_TOTAL>>>(
        Yh, Yl, W1h, W1l, nullptr, TOK_M, D_FF, D_MOD,
        nullptr, nullptr, 1, Fh, Fl, nullptr);
    gemm_mma<<<dim3(D_MOD / 64, TOK_M / 128), 256, GSM_TOTAL>>>(
        Fh, Fl, W2h, W2l, nullptr, TOK_M, D_MOD, D_FF,
        nullptr, S2, 0, Xh, Xl, nullptr);

    gemm_mma<<<dim3(CCH / 64, TOK_M / 128), 256, GSM_TOTAL>>>(
        Xh, Xl, Wch, Wcl, nullptr, TOK_M, CCH, D_MOD,
        nullptr, nullptr, 0, nullptr, nullptr, out);
}

// round 10
// speedup vs baseline: 2.3645x; 1.0546x over previous
#include <cuda_runtime.h>
#include <cuda_bf16.h>
#include <stdint.h>
#include <math.h>

// ---------------------------------------------------------------------------
// Problem constants: b=4, c=128, a=25, h=w=32
// Token order: m = ba*1024 + p (ba-major). Conv K order: k = tap*128 + c.
// ---------------------------------------------------------------------------
#define TOK_M   102400
#define D_MOD   256
#define D_FF    512
#define QKV_N   768
#define BA      100
#define PIX     1024
#define CCH     128
#define AA      25
#define KIN     1152

// ------------------------- scratch (static device) -------------------------
__device__ float g_T  [TOK_M * D_MOD];
__device__ float g_PE [TOK_M * D_MOD];
__device__ float g_QKV[TOK_M * QKV_N];
__device__ float g_S2 [TOK_M * D_MOD];

__device__ __nv_bfloat16 gA_hi[(size_t)TOK_M * KIN];
__device__ __nv_bfloat16 gA_lo[(size_t)TOK_M * KIN];
__device__ __nv_bfloat16 gX_hi[TOK_M * D_MOD],  gX_lo[TOK_M * D_MOD];
__device__ __nv_bfloat16 gAO_hi[TOK_M * D_MOD], gAO_lo[TOK_M * D_MOD];
__device__ __nv_bfloat16 gY_hi[TOK_M * D_MOD],  gY_lo[TOK_M * D_MOD];
__device__ __nv_bfloat16 gF_hi[TOK_M * D_FF],   gF_lo[TOK_M * D_FF];

__device__ __nv_bfloat16 gWmlp_hi [D_MOD * KIN],   gWmlp_lo [D_MOD * KIN];
__device__ __nv_bfloat16 gWqkv_hi [QKV_N * D_MOD], gWqkv_lo [QKV_N * D_MOD];
__device__ __nv_bfloat16 gWproj_hi[D_MOD * D_MOD], gWproj_lo[D_MOD * D_MOD];
__device__ __nv_bfloat16 gW1_hi   [D_FF * D_MOD],  gW1_lo   [D_FF * D_MOD];
__device__ __nv_bfloat16 gW2_hi   [D_MOD * D_FF],  gW2_lo   [D_MOD * D_FF];
__device__ __nv_bfloat16 gWc_hi   [CCH * D_MOD],   gWc_lo   [CCH * D_MOD];

// ---------------------------------------------------------------------------
// base-target-legal PTX helpers (sm_80+)
// ---------------------------------------------------------------------------
__device__ __forceinline__ uint32_t smem_u32(const void* p) {
    uint32_t a;
    asm("{ .reg .u64 t; cvta.to.shared.u64 t, %1; cvt.u32.u64 %0, t; }"
        : "=r"(a) : "l"(p));
    return a;
}
__device__ __forceinline__ void ldsm_x4(uint32_t* r, uint32_t addr) {
    asm volatile("ldmatrix.sync.aligned.m8n8.x4.shared.b16 {%0,%1,%2,%3}, [%4];"
        : "=r"(r[0]), "=r"(r[1]), "=r"(r[2]), "=r"(r[3]) : "r"(addr));
}
__device__ __forceinline__ void mma16816(float* c, const uint32_t* a, const uint32_t* b) {
    asm volatile(
        "mma.sync.aligned.m16n8k16.row.col.f32.bf16.bf16.f32 "
        "{%0,%1,%2,%3}, {%4,%5,%6,%7}, {%8,%9}, {%0,%1,%2,%3};"
        : "+f"(c[0]), "+f"(c[1]), "+f"(c[2]), "+f"(c[3])
        : "r"(a[0]), "r"(a[1]), "r"(a[2]), "r"(a[3]), "r"(b[0]), "r"(b[1]));
}
#define CP16(dst, src) \
    asm volatile("cp.async.cg.shared.global [%0], [%1], 16;" \
        :: "r"(dst), "l"(src) : "memory")
#define CP_COMMIT() asm volatile("cp.async.commit_group;" ::: "memory")
#define CP_WAIT0()  asm volatile("cp.async.wait_group 0;" ::: "memory")
#define CP_WAIT1()  asm volatile("cp.async.wait_group 1;" ::: "memory")

// ---------------------------------------------------------------------------
// bf16x3 HMMA GEMM v3. BM=128, BN=128, BK=32; 512 threads = 16 warps (4m x 4n),
// warp tile 32x32. 3-stage cp.async pipeline, one __syncthreads per chunk.
// B fragments via merged ldmatrix.x4. Doubles MMA-per-byte vs BN=64 version.
// ---------------------------------------------------------------------------
#define RS 40
#define SM_AH 0
#define SM_AL 10240
#define SM_BH 20480
#define SM_BL 30720
#define SM_BUF 40960
#define GSM_TOTAL (3 * SM_BUF)   // 122880

__global__ __launch_bounds__(512) void gemm_mma(
    const __nv_bfloat16* __restrict__ Ahi, const __nv_bfloat16* __restrict__ Alo,
    const __nv_bfloat16* __restrict__ Bhi, const __nv_bfloat16* __restrict__ Blo,
    float* __restrict__ C, int M, int N, int K,
    const float* __restrict__ bias, const float* __restrict__ resid, int relu,
    __nv_bfloat16* __restrict__ Ohi, __nv_bfloat16* __restrict__ Olo,
    float* __restrict__ sai)
{
    extern __shared__ char sm[];
    const uint32_t smb = smem_u32(sm);
    const int tid = threadIdx.x;
    const int lane = tid & 31;
    const int wid = tid >> 5;
    const int warpm = wid & 3;          // 0..3
    const int warpn = wid >> 2;         // 0..3
    const int m0 = blockIdx.y * 128;
    const int n0 = blockIdx.x * 128;

    // loaders: 512 threads; row = tid>>2 (0..127), seg = tid&3 (16B units)
    const int row = tid >> 2;
    const int seg = tid & 3;
    const uint32_t ld_sm_off = (uint32_t)row * (RS * 2) + seg * 16;
    const __nv_bfloat16* pAh = Ahi + (size_t)(m0 + row) * K + seg * 8;
    const __nv_bfloat16* pAl = Alo + (size_t)(m0 + row) * K + seg * 8;
    const __nv_bfloat16* pBh = Bhi + (size_t)(n0 + row) * K + seg * 8;
    const __nv_bfloat16* pBl = Blo + (size_t)(n0 + row) * K + seg * 8;

    const int nch = K >> 5;

#pragma unroll
    for (int pt = 0; pt < 2; pt++) {
        const uint32_t stg = (uint32_t)pt * SM_BUF;
        const size_t kc = (size_t)pt * 32;
        CP16(smb + stg + SM_AH + ld_sm_off, pAh + kc);
        CP16(smb + stg + SM_AL + ld_sm_off, pAl + kc);
        CP16(smb + stg + SM_BH + ld_sm_off, pBh + kc);
        CP16(smb + stg + SM_BL + ld_sm_off, pBl + kc);
        CP_COMMIT();
    }

    float acc[2][4][4];
#pragma unroll
    for (int im = 0; im < 2; im++)
#pragma unroll
        for (int in = 0; in < 4; in++)
#pragma unroll
            for (int r = 0; r < 4; r++) acc[im][in][r] = 0.f;

    const uint32_t a_ld_row = (uint32_t)(warpm * 32 + (lane & 15));
    const uint32_t a_ld_k8  = (uint32_t)((lane >> 4) * 8);
    // B x4 lane mapping: group = lane>>3: (nsub, khalf) = (group>>1, group&1)
    const uint32_t b_ld_row = (uint32_t)(warpn * 32 + ((lane >> 4) & 1) * 8 + (lane & 7));
    const uint32_t b_ld_k8  = (uint32_t)(((lane >> 3) & 1) * 8);

    int sc = 0;
    for (int t = 0; t < nch; t++) {
        if (t + 1 < nch) { CP_WAIT1(); } else { CP_WAIT0(); }
        __syncthreads();

        if (t + 2 < nch) {
            const int si = (sc >= 1) ? sc - 1 : 2;
            const uint32_t stg = (uint32_t)si * SM_BUF;
            const size_t kc = (size_t)(t + 2) * 32;
            CP16(smb + stg + SM_AH + ld_sm_off, pAh + kc);
            CP16(smb + stg + SM_AL + ld_sm_off, pAl + kc);
            CP16(smb + stg + SM_BH + ld_sm_off, pBh + kc);
            CP16(smb + stg + SM_BL + ld_sm_off, pBl + kc);
            CP_COMMIT();
        }

        const uint32_t cur = (uint32_t)sc * SM_BUF;
#pragma unroll
        for (int ks = 0; ks < 2; ks++) {
            uint32_t ah[2][4], al[2][4], bh[4][2], bl[4][2];
#pragma unroll
            for (int im = 0; im < 2; im++) {
                const uint32_t ao = cur +
                    ((a_ld_row + im * 16) * RS + ks * 16 + a_ld_k8) * 2;
                ldsm_x4(ah[im], smb + SM_AH + ao);
                ldsm_x4(al[im], smb + SM_AL + ao);
            }
#pragma unroll
            for (int p = 0; p < 2; p++) {
                const uint32_t bo = cur +
                    ((b_ld_row + p * 16) * RS + ks * 16 + b_ld_k8) * 2;
                uint32_t r[4];
                ldsm_x4(r, smb + SM_BH + bo);
                bh[2*p][0] = r[0]; bh[2*p][1] = r[1];
                bh[2*p+1][0] = r[2]; bh[2*p+1][1] = r[3];
                ldsm_x4(r, smb + SM_BL + bo);
                bl[2*p][0] = r[0]; bl[2*p][1] = r[1];
                bl[2*p+1][0] = r[2]; bl[2*p+1][1] = r[3];
            }
#pragma unroll
            for (int im = 0; im < 2; im++)
#pragma unroll
                for (int in = 0; in < 4; in++) {
                    mma16816(acc[im][in], ah[im], bh[in]);
                    mma16816(acc[im][in], ah[im], bl[in]);
                    mma16816(acc[im][in], al[im], bh[in]);
                }
        }
        sc = (sc >= 2) ? 0 : sc + 1;
    }

    // ---- epilogue ----
#pragma unroll
    for (int im = 0; im < 2; im++) {
#pragma unroll
        for (int in = 0; in < 4; in++) {
            const int mrow = m0 + warpm * 32 + im * 16 + (lane >> 2);
            const int ncol = n0 + warpn * 32 + in * 8 + (lane & 3) * 2;
#pragma unroll
            for (int r = 0; r < 2; r++) {
                const int m = mrow + r * 8;
                float v0 = acc[im][in][r * 2 + 0];
                float v1 = acc[im][in][r * 2 + 1];
                if (bias)  { v0 += bias[ncol]; v1 += bias[ncol + 1]; }
                if (relu)  { v0 = fmaxf(v0, 0.f); v1 = fmaxf(v1, 0.f); }
                if (resid) {
                    const float* rp = resid + (size_t)m * N + ncol;
                    v0 += rp[0]; v1 += rp[1];
                }
                if (C) {
                    float2 f2; f2.x = v0; f2.y = v1;
                    *(float2*)(C + (size_t)m * N + ncol) = f2;
                }
                if (Ohi) {
                    __nv_bfloat16 h0 = __float2bfloat16_rn(v0);
                    __nv_bfloat16 h1 = __float2bfloat16_rn(v1);
                    __nv_bfloat162 hv; hv.x = h0; hv.y = h1;
                    __nv_bfloat162 lv;
                    lv.x = __float2bfloat16_rn(v0 - __bfloat162float(h0));
                    lv.y = __float2bfloat16_rn(v1 - __bfloat162float(h1));
                    *(__nv_bfloat162*)(Ohi + (size_t)m * N + ncol) = hv;
                    *(__nv_bfloat162*)(Olo + (size_t)m * N + ncol) = lv;
                }
                if (sai) {
                    const int ba = m >> 10, p = m & 1023;
                    const int b_ = ba / AA, a_ = ba - b_ * AA;
                    sai[((size_t)(b_ * CCH + ncol)     * AA + a_) * PIX + p] = v0;
                    sai[((size_t)(b_ * CCH + ncol + 1) * AA + a_) * PIX + p] = v1;
                }
            }
        }
    }
}

// ---------------------------------------------------------------------------
// weight transpose + split kernels
// ---------------------------------------------------------------------------
__global__ void wsplit_kernel(const float* __restrict__ W, int K, int N,
                              __nv_bfloat16* __restrict__ oh,
                              __nv_bfloat16* __restrict__ ol)
{
    const int idx = blockIdx.x * 256 + threadIdx.x;
    if (idx >= K * N) return;
    const int k = idx / N, n = idx - k * N;
    const float v = W[idx];
    const __nv_bfloat16 h = __float2bfloat16_rn(v);
    oh[(size_t)n * K + k] = h;
    ol[(size_t)n * K + k] = __float2bfloat16_rn(v - __bfloat162float(h));
}

__global__ void wsplit_mlp(const float* __restrict__ W,
                           __nv_bfloat16* __restrict__ oh,
                           __nv_bfloat16* __restrict__ ol)
{
    const int idx = blockIdx.x * 256 + threadIdx.x;
    if (idx >= KIN * D_MOD) return;
    const int kk = idx / D_MOD, n = idx - kk * D_MOD;
    const int c = kk / 9, tap = kk - c * 9;
    const int kp = tap * 128 + c;
    const float v = W[idx];
    const __nv_bfloat16 h = __float2bfloat16_rn(v);
    oh[(size_t)n * KIN + kp] = h;
    ol[(size_t)n * KIN + kp] = __float2bfloat16_rn(v - __bfloat162float(h));
}

__global__ void split_kernel(const float* __restrict__ X, size_t n,
                             __nv_bfloat16* __restrict__ oh,
                             __nv_bfloat16* __restrict__ ol)
{
    const size_t i = (size_t)blockIdx.x * 256 + threadIdx.x;
    if (i >= n) return;
    const float v = X[i];
    const __nv_bfloat16 h = __float2bfloat16_rn(v);
    oh[i] = h;
    ol[i] = __float2bfloat16_rn(v - __bfloat162float(h));
}

// ---------------------------------------------------------------------------
// im2col (coalesced): A[m = ba*1024+p][k = tap*128+c] bf16 hi/lo.
// ---------------------------------------------------------------------------
__global__ __launch_bounds__(256) void im2col2(
    const float* __restrict__ src,
    __nv_bfloat16* __restrict__ Ahi, __nv_bfloat16* __restrict__ Alo)
{
    __shared__ float xs[32 * 321];
    const int tid = threadIdx.x;
    const int i0 = blockIdx.x * 8;
    const int c0 = blockIdx.y * 32;
    const int ba = blockIdx.z;
    const int b_ = ba / AA, a_ = ba - b_ * AA;

    for (int l = tid; l < 10240; l += 256) {
        const int c = l / 320;
        const int rem = l - c * 320;
        const int r = rem >> 5, col = rem & 31;
        const int ii = i0 - 1 + r;
        float v = 0.f;
        if (ii >= 0 && ii < 32)
            v = src[(((size_t)(b_ * CCH + c0 + c)) * AA + a_) * PIX + ii * 32 + col];
        xs[c * 321 + rem] = v;
    }
    __syncthreads();

    const int w = tid >> 5, lane = tid & 31;
    const int i = i0 + w;
    const float* xrow = xs + lane * 321;
    for (int j = 0; j < 32; j++) {
        const size_t m = (size_t)ba * PIX + i * 32 + j;
        const size_t mbase = m * KIN + c0 + lane;
#pragma unroll
        for (int tap = 0; tap < 9; tap++) {
            const int di = tap / 3, dj = tap - di * 3 - 1;
            const int jj = j + dj;
            float v = 0.f;
            if (jj >= 0 && jj < 32) v = xrow[(w + di) * 32 + jj];
            const __nv_bfloat16 h = __float2bfloat16_rn(v);
            Ahi[mbase + (size_t)tap * 128] = h;
            Alo[mbase + (size_t)tap * 128] =
                __float2bfloat16_rn(v - __bfloat162float(h));
        }
    }
}

// ---------------------------------------------------------------------------
// LayerNorm over D=256 -> bf16 hi/lo. Optional addsrc.
// ---------------------------------------------------------------------------
__global__ __launch_bounds__(256) void ln_kernel(
    const float* __restrict__ X, const float* __restrict__ addsrc,
    const float* __restrict__ g, const float* __restrict__ b,
    __nv_bfloat16* __restrict__ oh, __nv_bfloat16* __restrict__ ol)
{
    const size_t row = blockIdx.x;
    const int tid = threadIdx.x;
    __shared__ float red[8];

    float v = X[row * D_MOD + tid];
    if (addsrc) v += addsrc[row * D_MOD + tid];

    float s = v;
#pragma unroll
    for (int o = 16; o; o >>= 1) s += __shfl_xor_sync(0xffffffffu, s, o);
    if ((tid & 31) == 0) red[tid >> 5] = s;
    __syncthreads();
    float mean = 0.f;
#pragma unroll
    for (int i = 0; i < 8; i++) mean += red[i];
    mean *= (1.f / 256.f);
    __syncthreads();

    const float dev = v - mean;
    float q = dev * dev;
#pragma unroll
    for (int o = 16; o; o >>= 1) q += __shfl_xor_sync(0xffffffffu, q, o);
    if ((tid & 31) == 0) red[tid >> 5] = q;
    __syncthreads();
    float var = 0.f;
#pragma unroll
    for (int i = 0; i < 8; i++) var += red[i];
    var *= (1.f / 256.f);

    const float r = dev * rsqrtf(var + 1e-5f) * g[tid] + b[tid];
    const __nv_bfloat16 h = __float2bfloat16_rn(r);
    oh[row * D_MOD + tid] = h;
    ol[row * D_MOD + tid] = __float2bfloat16_rn(r - __bfloat162float(h));
}

// ---------------------------------------------------------------------------
// Fused attention v2 — conflict-free smem (tail-padded).
// ---------------------------------------------------------------------------
#define KTP 105
#define TAILPAD 64
#define ATT_SMEM_FLOATS (256 * KTP + 25600 + 256 + 800 + 800 + TAILPAD)
#define ATT_SMEM_BYTES  (ATT_SMEM_FLOATS * 4)

__global__ __launch_bounds__(256) void attn_kernel(
    const float* __restrict__ qkv,
    __nv_bfloat16* __restrict__ outh, __nv_bfloat16* __restrict__ outl,
    const float* __restrict__ Wl, const float* __restrict__ bl,
    const float* __restrict__ Ww, const float* __restrict__ bw,
    const float* __restrict__ lamb)
{
    extern __shared__ float smf[];
    float* Kt   = smf;
    float* Vs   = Kt + 256 * KTP;
    float* qs   = Vs + 25600;
    float* sraw = qs + 256;
    float* satt = sraw + 800;

    const int tid = threadIdx.x;
    const int g = tid >> 5, lane = tid & 31;
    const int bq = blockIdx.x;
    const float scale = 0.17677669529663687f;

    float wl[8], ww[8];
#pragma unroll
    for (int h = 0; h < 8; h++) { wl[h] = Wl[g * 8 + h]; ww[h] = Ww[g * 8 + h]; }
    const float blg = bl[g], bwg = bw[g];
    const float lam = 1.f + lamb[g];

    for (int idx = tid; idx < 25600; idx += 256) {
        const int m = idx >> 8, cc = idx & 255;
        const size_t rowb = ((size_t)m * PIX + bq) * QKV_N;
        Kt[cc * KTP + m] = qkv[rowb + 256 + cc];
        Vs[idx]          = qkv[rowb + 512 + cc];
    }
    __syncthreads();

    for (int n = 0; n < BA; n++) {
        qs[tid] = qkv[((size_t)n * PIX + bq) * QKV_N + tid] * scale;
        __syncthreads();

        const float qreg = qs[tid];
        float a0 = 0.f, a1 = 0.f, a2 = 0.f, a3 = 0.f;
        const float* kb = Kt + (g * 32) * KTP;
#pragma unroll
        for (int dd = 0; dd < 32; dd++) {
            const float qd = __shfl_sync(0xffffffffu, qreg, dd);
            const float* kr = kb + dd * KTP;
            a0 += qd * kr[lane];
            a1 += qd * kr[32 + lane];
            a2 += qd * kr[64 + lane];
            a3 += qd * kr[96 + lane];
        }
        sraw[g * 100 + lane]      = a0;
        sraw[g * 100 + 32 + lane] = a1;
        sraw[g * 100 + 64 + lane] = a2;
        if (lane < 4) sraw[g * 100 + 96 + lane] = a3;
        __syncthreads();

        float s0 = blg, s1 = blg, s2 = blg, s3 = blg;
#pragma unroll
        for (int h = 0; h < 8; h++) {
            const float* sr = sraw + h * 100;
            const float w = wl[h];
            s0 += w * sr[lane];
            s1 += w * sr[32 + lane];
            s2 += w * sr[64 + lane];
            s3 += w * sr[96 + lane];
        }
        if (lane >= 4) s3 = -1e30f;
        float mx = fmaxf(fmaxf(s0, s1), fmaxf(s2, s3));
#pragma unroll
        for (int o = 16; o; o >>= 1) mx = fmaxf(mx, __shfl_xor_sync(0xffffffffu, mx, o));
        float e0 = __expf(s0 - mx);
        float e1 = __expf(s1 - mx);
        float e2 = __expf(s2 - mx);
        float e3 = (lane < 4) ? __expf(s3 - mx) : 0.f;
        float sum = e0 + e1 + e2 + e3;
#pragma unroll
        for (int o = 16; o; o >>= 1) sum += __shfl_xor_sync(0xffffffffu, sum, o);
        const float inv = 1.f / sum;
        satt[g * 100 + lane]      = e0 * inv;
        satt[g * 100 + 32 + lane] = e1 * inv;
        satt[g * 100 + 64 + lane] = e2 * inv;
        if (lane < 4) satt[g * 100 + 96 + lane] = e3 * inv;
        __syncthreads();

        float w0 = bwg, w1 = bwg, w2 = bwg, w3 = bwg;
#pragma unroll
        for (int h = 0; h < 8; h++) {
            const float* sa = satt + h * 100;
            const float w = ww[h];
            w0 += w * sa[lane];
            w1 += w * sa[32 + lane];
            w2 += w * sa[64 + lane];
            w3 += w * sa[96 + lane];
        }
        w0 = 0.01f + (w0 - 0.01f) * lam;
        w1 = 0.01f + (w1 - 0.01f) * lam;
        w2 = 0.01f + (w2 - 0.01f) * lam;
        w3 = 0.01f + (w3 - 0.01f) * lam;

        float o = 0.f;
        const float* vb = Vs + g * 32 + lane;
#pragma unroll 4
        for (int sl = 0; sl < 32; sl++) {
            const float wm0 = __shfl_sync(0xffffffffu, w0, sl);
            const float wm1 = __shfl_sync(0xffffffffu, w1, sl);
            const float wm2 = __shfl_sync(0xffffffffu, w2, sl);
            o += wm0 * vb[sl * 256];
            o += wm1 * vb[(32 + sl) * 256];
            o += wm2 * vb[(64 + sl) * 256];
        }
#pragma unroll
        for (int sl = 0; sl < 4; sl++) {
            const float wm3 = __shfl_sync(0xffffffffu, w3, sl);
            o += wm3 * vb[(96 + sl) * 256];
        }
        const size_t oi = ((size_t)n * PIX + bq) * D_MOD + g * 32 + lane;
        const __nv_bfloat16 h = __float2bfloat16_rn(o);
        outh[oi] = h;
        outl[oi] = __float2bfloat16_rn(o - __bfloat162float(h));
    }
}

// ---------------------------------------------------------------------------
extern "C" void kernel_launch(void* const* d_in, const int* in_sizes, int n_in,
                              void* d_out, int out_size)
{
    const float* buffer  = (const float*)d_in[0];
    const float* spa_pos = (const float*)d_in[1];
    const float* W_mlp   = (const float*)d_in[2];
    const float* g1      = (const float*)d_in[3];
    const float* b1      = (const float*)d_in[4];
    const float* Wqkv    = (const float*)d_in[5];
    const float* Wproj   = (const float*)d_in[6];
    const float* bproj   = (const float*)d_in[7];
    const float* Wl      = (const float*)d_in[8];
    const float* bl      = (const float*)d_in[9];
    const float* Ww      = (const float*)d_in[10];
    const float* bw      = (const float*)d_in[11];
    const float* lamb    = (const float*)d_in[12];
    const float* g2      = (const float*)d_in[13];
    const float* b2      = (const float*)d_in[14];
    const float* W1      = (const float*)d_in[15];
    const float* W2      = (const float*)d_in[16];
    const float* Wconv   = (const float*)d_in[17];
    float* out = (float*)d_out;

    float *T, *PE, *QKV, *S2;
    cudaGetSymbolAddress((void**)&T,   g_T);
    cudaGetSymbolAddress((void**)&PE,  g_PE);
    cudaGetSymbolAddress((void**)&QKV, g_QKV);
    cudaGetSymbolAddress((void**)&S2,  g_S2);

    __nv_bfloat16 *Ah, *Al, *Xh, *Xl, *AOh, *AOl, *Yh, *Yl, *Fh, *Fl;
    __nv_bfloat16 *Wmh, *Wml, *Wqh, *Wql, *Wph, *Wpl, *W1h, *W1l, *W2h, *W2l, *Wch, *Wcl;
    cudaGetSymbolAddress((void**)&Ah,  gA_hi);   cudaGetSymbolAddress((void**)&Al,  gA_lo);
    cudaGetSymbolAddress((void**)&Xh,  gX_hi);   cudaGetSymbolAddress((void**)&Xl,  gX_lo);
    cudaGetSymbolAddress((void**)&AOh, gAO_hi);  cudaGetSymbolAddress((void**)&AOl, gAO_lo);
    cudaGetSymbolAddress((void**)&Yh,  gY_hi);   cudaGetSymbolAddress((void**)&Yl,  gY_lo);
    cudaGetSymbolAddress((void**)&Fh,  gF_hi);   cudaGetSymbolAddress((void**)&Fl,  gF_lo);
    cudaGetSymbolAddress((void**)&Wmh, gWmlp_hi);  cudaGetSymbolAddress((void**)&Wml, gWmlp_lo);
    cudaGetSymbolAddress((void**)&Wqh, gWqkv_hi);  cudaGetSymbolAddress((void**)&Wql, gWqkv_lo);
    cudaGetSymbolAddress((void**)&Wph, gWproj_hi); cudaGetSymbolAddress((void**)&Wpl, gWproj_lo);
    cudaGetSymbolAddress((void**)&W1h, gW1_hi);    cudaGetSymbolAddress((void**)&W1l, gW1_lo);
    cudaGetSymbolAddress((void**)&W2h, gW2_hi);    cudaGetSymbolAddress((void**)&W2l, gW2_lo);
    cudaGetSymbolAddress((void**)&Wch, gWc_hi);    cudaGetSymbolAddress((void**)&Wcl, gWc_lo);

    cudaFuncSetAttribute(attn_kernel, cudaFuncAttributeMaxDynamicSharedMemorySize,
                         ATT_SMEM_BYTES);
    cudaFuncSetAttribute(gemm_mma, cudaFuncAttributeMaxDynamicSharedMemorySize,
                         GSM_TOTAL);

    // App launch #4 = ncu capture target (conv GEMM).
    im2col2<<<dim3(4, 4, BA), 256>>>(buffer, Ah, Al);
    wsplit_mlp<<<(KIN * D_MOD + 255) / 256, 256>>>(W_mlp, Wmh, Wml);
    wsplit_kernel<<<(D_MOD * QKV_N + 255) / 256, 256>>>(Wqkv, D_MOD, QKV_N, Wqh, Wql);
    gemm_mma<<<dim3(D_MOD / 128, TOK_M / 128), 512, GSM_TOTAL>>>(
        Ah, Al, Wmh, Wml, T, TOK_M, D_MOD, KIN,
        nullptr, nullptr, 0, nullptr, nullptr, nullptr);
    im2col2<<<dim3(4, 4, BA), 256>>>(spa_pos, Ah, Al);
    gemm_mma<<<dim3(D_MOD / 128, TOK_M / 128), 512, GSM_TOTAL>>>(
        Ah, Al, Wmh, Wml, PE, TOK_M, D_MOD, KIN,
        nullptr, nullptr, 0, nullptr, nullptr, nullptr);
    wsplit_kernel<<<(D_MOD * D_MOD + 255) / 256, 256>>>(Wproj, D_MOD, D_MOD, Wph, Wpl);
    wsplit_kernel<<<(D_MOD * D_FF + 255) / 256, 256>>>(W1, D_MOD, D_FF, W1h, W1l);
    wsplit_kernel<<<(D_FF * D_MOD + 255) / 256, 256>>>(W2, D_FF, D_MOD, W2h, W2l);
    split_kernel<<<(CCH * D_MOD + 255) / 256, 256>>>(Wconv, (size_t)CCH * D_MOD, Wch, Wcl);

    ln_kernel<<<TOK_M, 256>>>(T, PE, g1, b1, Xh, Xl);

    gemm_mma<<<dim3(QKV_N / 128, TOK_M / 128), 512, GSM_TOTAL>>>(
        Xh, Xl, Wqh, Wql, QKV, TOK_M, QKV_N, D_MOD,
        nullptr, nullptr, 0, nullptr, nullptr, nullptr);

    attn_kernel<<<PIX, 256, ATT_SMEM_BYTES>>>(QKV, AOh, AOl, Wl, bl, Ww, bw, lamb);

    gemm_mma<<<dim3(D_MOD / 128, TOK_M / 128), 512, GSM_TOTAL>>>(
        AOh, AOl, Wph, Wpl, S2, TOK_M, D_MOD, D_MOD,
        bproj, T, 0, nullptr, nullptr, nullptr);

    ln_kernel<<<TOK_M, 256>>>(S2, nullptr, g2, b2, Yh, Yl);

    gemm_mma<<<dim3(D_FF / 128, TOK_M / 128), 512, GSM_TOTAL>>>(
        Yh, Yl, W1h, W1l, nullptr, TOK_M, D_FF, D_MOD,
        nullptr, nullptr, 1, Fh, Fl, nullptr);
    gemm_mma<<<dim3(D_MOD / 128, TOK_M / 128), 512, GSM_TOTAL>>>(
        Fh, Fl, W2h, W2l, nullptr, TOK_M, D_MOD, D_FF,
        nullptr, S2, 0, Xh, Xl, nullptr);

    gemm_mma<<<dim3(CCH / 128, TOK_M / 128), 512, GSM_TOTAL>>>(
        Xh, Xl, Wch, Wcl, nullptr, TOK_M, CCH, D_MOD,
        nullptr, nullptr, 0, nullptr, nullptr, out);
}

// round 11
// speedup vs baseline: 2.8575x; 1.2085x over previous
#include <cuda_runtime.h>
#include <cuda_bf16.h>
#include <stdint.h>
#include <math.h>

// ---------------------------------------------------------------------------
// Problem constants: b=4, c=128, a=25, h=w=32
// Token order: m = ba*1024 + p (ba-major). Conv K order: k = tap*128 + c.
// ---------------------------------------------------------------------------
#define TOK_M   102400
#define D_MOD   256
#define D_FF    512
#define QKV_N   768
#define BA      100
#define PIX     1024
#define CCH     128
#define AA      25
#define KIN     1152

// ------------------------- scratch (static device) -------------------------
__device__ float g_T  [TOK_M * D_MOD];
__device__ float g_PE [TOK_M * D_MOD];
__device__ float g_QKV[TOK_M * QKV_N];
__device__ float g_S2 [TOK_M * D_MOD];

__device__ __nv_bfloat16 gA_hi[(size_t)TOK_M * KIN];
__device__ __nv_bfloat16 gA_lo[(size_t)TOK_M * KIN];
__device__ __nv_bfloat16 gX_hi[TOK_M * D_MOD],  gX_lo[TOK_M * D_MOD];
__device__ __nv_bfloat16 gAO_hi[TOK_M * D_MOD], gAO_lo[TOK_M * D_MOD];
__device__ __nv_bfloat16 gY_hi[TOK_M * D_MOD],  gY_lo[TOK_M * D_MOD];
__device__ __nv_bfloat16 gF_hi[TOK_M * D_FF],   gF_lo[TOK_M * D_FF];

__device__ __nv_bfloat16 gWmlp_hi [D_MOD * KIN],   gWmlp_lo [D_MOD * KIN];
__device__ __nv_bfloat16 gWqkv_hi [QKV_N * D_MOD], gWqkv_lo [QKV_N * D_MOD];
__device__ __nv_bfloat16 gWproj_hi[D_MOD * D_MOD], gWproj_lo[D_MOD * D_MOD];
__device__ __nv_bfloat16 gW1_hi   [D_FF * D_MOD],  gW1_lo   [D_FF * D_MOD];
__device__ __nv_bfloat16 gW2_hi   [D_MOD * D_FF],  gW2_lo   [D_MOD * D_FF];
__device__ __nv_bfloat16 gWc_hi   [CCH * D_MOD],   gWc_lo   [CCH * D_MOD];

// ---------------------------------------------------------------------------
// base-target-legal PTX helpers (sm_80+)
// ---------------------------------------------------------------------------
__device__ __forceinline__ uint32_t smem_u32(const void* p) {
    uint32_t a;
    asm("{ .reg .u64 t; cvta.to.shared.u64 t, %1; cvt.u32.u64 %0, t; }"
        : "=r"(a) : "l"(p));
    return a;
}
__device__ __forceinline__ void ldsm_x4(uint32_t* r, uint32_t addr) {
    asm volatile("ldmatrix.sync.aligned.m8n8.x4.shared.b16 {%0,%1,%2,%3}, [%4];"
        : "=r"(r[0]), "=r"(r[1]), "=r"(r[2]), "=r"(r[3]) : "r"(addr));
}
__device__ __forceinline__ void mma16816(float* c, const uint32_t* a, const uint32_t* b) {
    asm volatile(
        "mma.sync.aligned.m16n8k16.row.col.f32.bf16.bf16.f32 "
        "{%0,%1,%2,%3}, {%4,%5,%6,%7}, {%8,%9}, {%0,%1,%2,%3};"
        : "+f"(c[0]), "+f"(c[1]), "+f"(c[2]), "+f"(c[3])
        : "r"(a[0]), "r"(a[1]), "r"(a[2]), "r"(a[3]), "r"(b[0]), "r"(b[1]));
}
#define CP16(dst, src) \
    asm volatile("cp.async.cg.shared.global [%0], [%1], 16;" \
        :: "r"(dst), "l"(src) : "memory")
#define CP_COMMIT() asm volatile("cp.async.commit_group;" ::: "memory")
#define CP_WAIT0()  asm volatile("cp.async.wait_group 0;" ::: "memory")
#define CP_WAIT1()  asm volatile("cp.async.wait_group 1;" ::: "memory")

// ---------------------------------------------------------------------------
// bf16x3 HMMA GEMM v3 (unchanged from round 10; validated 54% tensor).
// BM=128, BN=128, BK=32; 512 threads = 16 warps (4m x 4n), warp tile 32x32.
// ---------------------------------------------------------------------------
#define RS 40
#define SM_AH 0
#define SM_AL 10240
#define SM_BH 20480
#define SM_BL 30720
#define SM_BUF 40960
#define GSM_TOTAL (3 * SM_BUF)   // 122880

__global__ __launch_bounds__(512) void gemm_mma(
    const __nv_bfloat16* __restrict__ Ahi, const __nv_bfloat16* __restrict__ Alo,
    const __nv_bfloat16* __restrict__ Bhi, const __nv_bfloat16* __restrict__ Blo,
    float* __restrict__ C, int M, int N, int K,
    const float* __restrict__ bias, const float* __restrict__ resid, int relu,
    __nv_bfloat16* __restrict__ Ohi, __nv_bfloat16* __restrict__ Olo,
    float* __restrict__ sai)
{
    extern __shared__ char sm[];
    const uint32_t smb = smem_u32(sm);
    const int tid = threadIdx.x;
    const int lane = tid & 31;
    const int wid = tid >> 5;
    const int warpm = wid & 3;
    const int warpn = wid >> 2;
    const int m0 = blockIdx.y * 128;
    const int n0 = blockIdx.x * 128;

    const int row = tid >> 2;
    const int seg = tid & 3;
    const uint32_t ld_sm_off = (uint32_t)row * (RS * 2) + seg * 16;
    const __nv_bfloat16* pAh = Ahi + (size_t)(m0 + row) * K + seg * 8;
    const __nv_bfloat16* pAl = Alo + (size_t)(m0 + row) * K + seg * 8;
    const __nv_bfloat16* pBh = Bhi + (size_t)(n0 + row) * K + seg * 8;
    const __nv_bfloat16* pBl = Blo + (size_t)(n0 + row) * K + seg * 8;

    const int nch = K >> 5;

#pragma unroll
    for (int pt = 0; pt < 2; pt++) {
        const uint32_t stg = (uint32_t)pt * SM_BUF;
        const size_t kc = (size_t)pt * 32;
        CP16(smb + stg + SM_AH + ld_sm_off, pAh + kc);
        CP16(smb + stg + SM_AL + ld_sm_off, pAl + kc);
        CP16(smb + stg + SM_BH + ld_sm_off, pBh + kc);
        CP16(smb + stg + SM_BL + ld_sm_off, pBl + kc);
        CP_COMMIT();
    }

    float acc[2][4][4];
#pragma unroll
    for (int im = 0; im < 2; im++)
#pragma unroll
        for (int in = 0; in < 4; in++)
#pragma unroll
            for (int r = 0; r < 4; r++) acc[im][in][r] = 0.f;

    const uint32_t a_ld_row = (uint32_t)(warpm * 32 + (lane & 15));
    const uint32_t a_ld_k8  = (uint32_t)((lane >> 4) * 8);
    const uint32_t b_ld_row = (uint32_t)(warpn * 32 + ((lane >> 4) & 1) * 8 + (lane & 7));
    const uint32_t b_ld_k8  = (uint32_t)(((lane >> 3) & 1) * 8);

    int sc = 0;
    for (int t = 0; t < nch; t++) {
        if (t + 1 < nch) { CP_WAIT1(); } else { CP_WAIT0(); }
        __syncthreads();

        if (t + 2 < nch) {
            const int si = (sc >= 1) ? sc - 1 : 2;
            const uint32_t stg = (uint32_t)si * SM_BUF;
            const size_t kc = (size_t)(t + 2) * 32;
            CP16(smb + stg + SM_AH + ld_sm_off, pAh + kc);
            CP16(smb + stg + SM_AL + ld_sm_off, pAl + kc);
            CP16(smb + stg + SM_BH + ld_sm_off, pBh + kc);
            CP16(smb + stg + SM_BL + ld_sm_off, pBl + kc);
            CP_COMMIT();
        }

        const uint32_t cur = (uint32_t)sc * SM_BUF;
#pragma unroll
        for (int ks = 0; ks < 2; ks++) {
            uint32_t ah[2][4], al[2][4], bh[4][2], bl[4][2];
#pragma unroll
            for (int im = 0; im < 2; im++) {
                const uint32_t ao = cur +
                    ((a_ld_row + im * 16) * RS + ks * 16 + a_ld_k8) * 2;
                ldsm_x4(ah[im], smb + SM_AH + ao);
                ldsm_x4(al[im], smb + SM_AL + ao);
            }
#pragma unroll
            for (int p = 0; p < 2; p++) {
                const uint32_t bo = cur +
                    ((b_ld_row + p * 16) * RS + ks * 16 + b_ld_k8) * 2;
                uint32_t r[4];
                ldsm_x4(r, smb + SM_BH + bo);
                bh[2*p][0] = r[0]; bh[2*p][1] = r[1];
                bh[2*p+1][0] = r[2]; bh[2*p+1][1] = r[3];
                ldsm_x4(r, smb + SM_BL + bo);
                bl[2*p][0] = r[0]; bl[2*p][1] = r[1];
                bl[2*p+1][0] = r[2]; bl[2*p+1][1] = r[3];
            }
#pragma unroll
            for (int im = 0; im < 2; im++)
#pragma unroll
                for (int in = 0; in < 4; in++) {
                    mma16816(acc[im][in], ah[im], bh[in]);
                    mma16816(acc[im][in], ah[im], bl[in]);
                    mma16816(acc[im][in], al[im], bh[in]);
                }
        }
        sc = (sc >= 2) ? 0 : sc + 1;
    }

    // ---- epilogue ----
#pragma unroll
    for (int im = 0; im < 2; im++) {
#pragma unroll
        for (int in = 0; in < 4; in++) {
            const int mrow = m0 + warpm * 32 + im * 16 + (lane >> 2);
            const int ncol = n0 + warpn * 32 + in * 8 + (lane & 3) * 2;
#pragma unroll
            for (int r = 0; r < 2; r++) {
                const int m = mrow + r * 8;
                float v0 = acc[im][in][r * 2 + 0];
                float v1 = acc[im][in][r * 2 + 1];
                if (bias)  { v0 += bias[ncol]; v1 += bias[ncol + 1]; }
                if (relu)  { v0 = fmaxf(v0, 0.f); v1 = fmaxf(v1, 0.f); }
                if (resid) {
                    const float* rp = resid + (size_t)m * N + ncol;
                    v0 += rp[0]; v1 += rp[1];
                }
                if (C) {
                    float2 f2; f2.x = v0; f2.y = v1;
                    *(float2*)(C + (size_t)m * N + ncol) = f2;
                }
                if (Ohi) {
                    __nv_bfloat16 h0 = __float2bfloat16_rn(v0);
                    __nv_bfloat16 h1 = __float2bfloat16_rn(v1);
                    __nv_bfloat162 hv; hv.x = h0; hv.y = h1;
                    __nv_bfloat162 lv;
                    lv.x = __float2bfloat16_rn(v0 - __bfloat162float(h0));
                    lv.y = __float2bfloat16_rn(v1 - __bfloat162float(h1));
                    *(__nv_bfloat162*)(Ohi + (size_t)m * N + ncol) = hv;
                    *(__nv_bfloat162*)(Olo + (size_t)m * N + ncol) = lv;
                }
                if (sai) {
                    const int ba = m >> 10, p = m & 1023;
                    const int b_ = ba / AA, a_ = ba - b_ * AA;
                    sai[((size_t)(b_ * CCH + ncol)     * AA + a_) * PIX + p] = v0;
                    sai[((size_t)(b_ * CCH + ncol + 1) * AA + a_) * PIX + p] = v1;
                }
            }
        }
    }
}

// ---------------------------------------------------------------------------
// weight transpose + split kernels
// ---------------------------------------------------------------------------
__global__ void wsplit_kernel(const float* __restrict__ W, int K, int N,
                              __nv_bfloat16* __restrict__ oh,
                              __nv_bfloat16* __restrict__ ol)
{
    const int idx = blockIdx.x * 256 + threadIdx.x;
    if (idx >= K * N) return;
    const int k = idx / N, n = idx - k * N;
    const float v = W[idx];
    const __nv_bfloat16 h = __float2bfloat16_rn(v);
    oh[(size_t)n * K + k] = h;
    ol[(size_t)n * K + k] = __float2bfloat16_rn(v - __bfloat162float(h));
}

__global__ void wsplit_mlp(const float* __restrict__ W,
                           __nv_bfloat16* __restrict__ oh,
                           __nv_bfloat16* __restrict__ ol)
{
    const int idx = blockIdx.x * 256 + threadIdx.x;
    if (idx >= KIN * D_MOD) return;
    const int kk = idx / D_MOD, n = idx - kk * D_MOD;
    const int c = kk / 9, tap = kk - c * 9;
    const int kp = tap * 128 + c;
    const float v = W[idx];
    const __nv_bfloat16 h = __float2bfloat16_rn(v);
    oh[(size_t)n * KIN + kp] = h;
    ol[(size_t)n * KIN + kp] = __float2bfloat16_rn(v - __bfloat162float(h));
}

__global__ void split_kernel(const float* __restrict__ X, size_t n,
                             __nv_bfloat16* __restrict__ oh,
                             __nv_bfloat16* __restrict__ ol)
{
    const size_t i = (size_t)blockIdx.x * 256 + threadIdx.x;
    if (i >= n) return;
    const float v = X[i];
    const __nv_bfloat16 h = __float2bfloat16_rn(v);
    oh[i] = h;
    ol[i] = __float2bfloat16_rn(v - __bfloat162float(h));
}

// ---------------------------------------------------------------------------
// im2col (coalesced): A[m = ba*1024+p][k = tap*128+c] bf16 hi/lo.
// ---------------------------------------------------------------------------
__global__ __launch_bounds__(256) void im2col2(
    const float* __restrict__ src,
    __nv_bfloat16* __restrict__ Ahi, __nv_bfloat16* __restrict__ Alo)
{
    __shared__ float xs[32 * 321];
    const int tid = threadIdx.x;
    const int i0 = blockIdx.x * 8;
    const int c0 = blockIdx.y * 32;
    const int ba = blockIdx.z;
    const int b_ = ba / AA, a_ = ba - b_ * AA;

    for (int l = tid; l < 10240; l += 256) {
        const int c = l / 320;
        const int rem = l - c * 320;
        const int r = rem >> 5, col = rem & 31;
        const int ii = i0 - 1 + r;
        float v = 0.f;
        if (ii >= 0 && ii < 32)
            v = src[(((size_t)(b_ * CCH + c0 + c)) * AA + a_) * PIX + ii * 32 + col];
        xs[c * 321 + rem] = v;
    }
    __syncthreads();

    const int w = tid >> 5, lane = tid & 31;
    const int i = i0 + w;
    const float* xrow = xs + lane * 321;
    for (int j = 0; j < 32; j++) {
        const size_t m = (size_t)ba * PIX + i * 32 + j;
        const size_t mbase = m * KIN + c0 + lane;
#pragma unroll
        for (int tap = 0; tap < 9; tap++) {
            const int di = tap / 3, dj = tap - di * 3 - 1;
            const int jj = j + dj;
            float v = 0.f;
            if (jj >= 0 && jj < 32) v = xrow[(w + di) * 32 + jj];
            const __nv_bfloat16 h = __float2bfloat16_rn(v);
            Ahi[mbase + (size_t)tap * 128] = h;
            Alo[mbase + (size_t)tap * 128] =
                __float2bfloat16_rn(v - __bfloat162float(h));
        }
    }
}

// ---------------------------------------------------------------------------
// LayerNorm over D=256 -> bf16 hi/lo. Optional addsrc.
// ---------------------------------------------------------------------------
__global__ __launch_bounds__(256) void ln_kernel(
    const float* __restrict__ X, const float* __restrict__ addsrc,
    const float* __restrict__ g, const float* __restrict__ b,
    __nv_bfloat16* __restrict__ oh, __nv_bfloat16* __restrict__ ol)
{
    const size_t row = blockIdx.x;
    const int tid = threadIdx.x;
    __shared__ float red[8];

    float v = X[row * D_MOD + tid];
    if (addsrc) v += addsrc[row * D_MOD + tid];

    float s = v;
#pragma unroll
    for (int o = 16; o; o >>= 1) s += __shfl_xor_sync(0xffffffffu, s, o);
    if ((tid & 31) == 0) red[tid >> 5] = s;
    __syncthreads();
    float mean = 0.f;
#pragma unroll
    for (int i = 0; i < 8; i++) mean += red[i];
    mean *= (1.f / 256.f);
    __syncthreads();

    const float dev = v - mean;
    float q = dev * dev;
#pragma unroll
    for (int o = 16; o; o >>= 1) q += __shfl_xor_sync(0xffffffffu, q, o);
    if ((tid & 31) == 0) red[tid >> 5] = q;
    __syncthreads();
    float var = 0.f;
#pragma unroll
    for (int i = 0; i < 8; i++) var += red[i];
    var *= (1.f / 256.f);

    const float r = dev * rsqrtf(var + 1e-5f) * g[tid] + b[tid];
    const __nv_bfloat16 h = __float2bfloat16_rn(r);
    oh[row * D_MOD + tid] = h;
    ol[row * D_MOD + tid] = __float2bfloat16_rn(r - __bfloat162float(h));
}

// ---------------------------------------------------------------------------
// Fused attention v3 — 4-query batching.
// Kt[cc][m] pad 101 (odd -> conflict-free), Vs[m][cc]. Warp g owns head g.
// K/V smem reads amortized over 4 queries; q in registers (shfl broadcast);
// 2 barriers per 4-query block. sraw/satt overreads land in-bounds (TAILPAD).
// smem = 256*101 + 25600 + 4*800 + 4*800 + 64 = 57920 floats = 231,680 B.
// ---------------------------------------------------------------------------
#define KTP 101
#define TAILPAD 64
#define ATT_SMEM_FLOATS (256 * KTP + 25600 + 3200 + 3200 + TAILPAD)
#define ATT_SMEM_BYTES  (ATT_SMEM_FLOATS * 4)

__global__ __launch_bounds__(256) void attn_kernel(
    const float* __restrict__ qkv,
    __nv_bfloat16* __restrict__ outh, __nv_bfloat16* __restrict__ outl,
    const float* __restrict__ Wl, const float* __restrict__ bl,
    const float* __restrict__ Ww, const float* __restrict__ bw,
    const float* __restrict__ lamb)
{
    extern __shared__ float smf[];
    float* Kt   = smf;                  // [256][101]
    float* Vs   = Kt + 256 * KTP;       // [100][256]
    float* sraw = Vs + 25600;           // [4][800]
    float* satt = sraw + 3200;          // [4][800] + TAILPAD

    const int tid = threadIdx.x;
    const int g = tid >> 5, lane = tid & 31;
    const int bq = blockIdx.x;
    const float scale = 0.17677669529663687f;

    float wl[8], ww[8];
#pragma unroll
    for (int h = 0; h < 8; h++) { wl[h] = Wl[g * 8 + h]; ww[h] = Ww[g * 8 + h]; }
    const float blg = bl[g], bwg = bw[g];
    const float lam = 1.f + lamb[g];

    for (int idx = tid; idx < 25600; idx += 256) {
        const int m = idx >> 8, cc = idx & 255;
        const size_t rowb = ((size_t)m * PIX + bq) * QKV_N;
        Kt[cc * KTP + m] = qkv[rowb + 256 + cc];
        Vs[idx]          = qkv[rowb + 512 + cc];
    }
    __syncthreads();

    for (int n = 0; n < BA; n += 4) {
        // q for 4 queries into registers (channel = tid)
        float qr[4];
#pragma unroll
        for (int q = 0; q < 4; q++)
            qr[q] = qkv[((size_t)(n + q) * PIX + bq) * QKV_N + tid] * scale;

        // ---- scores: sraw[q][g][m] = q_{q,g} . k_{g,m}; K read once per 4q
        float a[4][4];
#pragma unroll
        for (int q = 0; q < 4; q++)
#pragma unroll
            for (int r = 0; r < 4; r++) a[q][r] = 0.f;
        const float* kb = Kt + (g * 32) * KTP;
#pragma unroll
        for (int dd = 0; dd < 32; dd++) {
            float qd[4];
#pragma unroll
            for (int q = 0; q < 4; q++)
                qd[q] = __shfl_sync(0xffffffffu, qr[q], dd);
            const float* kr = kb + dd * KTP;
            const float k0 = kr[lane];
            const float k1 = kr[32 + lane];
            const float k2 = kr[64 + lane];
            const float k3 = kr[96 + lane];   // lanes>=4 read Vs (masked later)
#pragma unroll
            for (int q = 0; q < 4; q++) {
                a[q][0] += qd[q] * k0;
                a[q][1] += qd[q] * k1;
                a[q][2] += qd[q] * k2;
                a[q][3] += qd[q] * k3;
            }
        }
#pragma unroll
        for (int q = 0; q < 4; q++) {
            float* srq = sraw + q * 800 + g * 100;
            srq[lane]      = a[q][0];
            srq[32 + lane] = a[q][1];
            srq[64 + lane] = a[q][2];
            if (lane < 4) srq[96 + lane] = a[q][3];
        }
        __syncthreads();                       // sync B

        // ---- talking-heads pre-mix + softmax per query
#pragma unroll
        for (int q = 0; q < 4; q++) {
            float s0 = blg, s1 = blg, s2 = blg, s3 = blg;
#pragma unroll
            for (int h = 0; h < 8; h++) {
                const float* sr = sraw + q * 800 + h * 100;
                const float w = wl[h];
                s0 += w * sr[lane];
                s1 += w * sr[32 + lane];
                s2 += w * sr[64 + lane];
                s3 += w * sr[96 + lane];       // garbage lanes>=4, masked
            }
            if (lane >= 4) s3 = -1e30f;
            float mx = fmaxf(fmaxf(s0, s1), fmaxf(s2, s3));
#pragma unroll
            for (int o = 16; o; o >>= 1) mx = fmaxf(mx, __shfl_xor_sync(0xffffffffu, mx, o));
            float e0 = __expf(s0 - mx);
            float e1 = __expf(s1 - mx);
            float e2 = __expf(s2 - mx);
            float e3 = (lane < 4) ? __expf(s3 - mx) : 0.f;
            float sum = e0 + e1 + e2 + e3;
#pragma unroll
            for (int o = 16; o; o >>= 1) sum += __shfl_xor_sync(0xffffffffu, sum, o);
            const float inv = 1.f / sum;
            float* saq = satt + q * 800 + g * 100;
            saq[lane]      = e0 * inv;
            saq[32 + lane] = e1 * inv;
            saq[64 + lane] = e2 * inv;
            if (lane < 4) saq[96 + lane] = e3 * inv;
        }
        __syncthreads();                       // sync C

        // ---- post-mix + attnscale (registers, per query)
        float w4[4][4];
#pragma unroll
        for (int q = 0; q < 4; q++) {
            float w0 = bwg, w1 = bwg, w2 = bwg, w3 = bwg;
#pragma unroll
            for (int h = 0; h < 8; h++) {
                const float* sa = satt + q * 800 + h * 100;
                const float w = ww[h];
                w0 += w * sa[lane];
                w1 += w * sa[32 + lane];
                w2 += w * sa[64 + lane];
                w3 += w * sa[96 + lane];       // in-bounds via TAILPAD, masked
            }
            w4[q][0] = 0.01f + (w0 - 0.01f) * lam;
            w4[q][1] = 0.01f + (w1 - 0.01f) * lam;
            w4[q][2] = 0.01f + (w2 - 0.01f) * lam;
            w4[q][3] = 0.01f + (w3 - 0.01f) * lam;
        }

        // ---- AV: V read once per 4 queries
        float o4[4] = {0.f, 0.f, 0.f, 0.f};
        const float* vb = Vs + g * 32 + lane;
#pragma unroll 4
        for (int sl = 0; sl < 32; sl++) {
            const float v0 = vb[sl * 256];
            const float v1 = vb[(32 + sl) * 256];
            const float v2 = vb[(64 + sl) * 256];
#pragma unroll
            for (int q = 0; q < 4; q++) {
                o4[q] += __shfl_sync(0xffffffffu, w4[q][0], sl) * v0;
                o4[q] += __shfl_sync(0xffffffffu, w4[q][1], sl) * v1;
                o4[q] += __shfl_sync(0xffffffffu, w4[q][2], sl) * v2;
            }
        }
#pragma unroll
        for (int sl = 0; sl < 4; sl++) {
            const float v3 = vb[(96 + sl) * 256];
#pragma unroll
            for (int q = 0; q < 4; q++)
                o4[q] += __shfl_sync(0xffffffffu, w4[q][3], sl) * v3;
        }
#pragma unroll
        for (int q = 0; q < 4; q++) {
            const size_t oi = ((size_t)(n + q) * PIX + bq) * D_MOD + g * 32 + lane;
            const __nv_bfloat16 h = __float2bfloat16_rn(o4[q]);
            outh[oi] = h;
            outl[oi] = __float2bfloat16_rn(o4[q] - __bfloat162float(h));
        }
    }
}

// ---------------------------------------------------------------------------
extern "C" void kernel_launch(void* const* d_in, const int* in_sizes, int n_in,
                              void* d_out, int out_size)
{
    const float* buffer  = (const float*)d_in[0];
    const float* spa_pos = (const float*)d_in[1];
    const float* W_mlp   = (const float*)d_in[2];
    const float* g1      = (const float*)d_in[3];
    const float* b1      = (const float*)d_in[4];
    const float* Wqkv    = (const float*)d_in[5];
    const float* Wproj   = (const float*)d_in[6];
    const float* bproj   = (const float*)d_in[7];
    const float* Wl      = (const float*)d_in[8];
    const float* bl      = (const float*)d_in[9];
    const float* Ww      = (const float*)d_in[10];
    const float* bw      = (const float*)d_in[11];
    const float* lamb    = (const float*)d_in[12];
    const float* g2      = (const float*)d_in[13];
    const float* b2      = (const float*)d_in[14];
    const float* W1      = (const float*)d_in[15];
    const float* W2      = (const float*)d_in[16];
    const float* Wconv   = (const float*)d_in[17];
    float* out = (float*)d_out;

    float *T, *PE, *QKV, *S2;
    cudaGetSymbolAddress((void**)&T,   g_T);
    cudaGetSymbolAddress((void**)&PE,  g_PE);
    cudaGetSymbolAddress((void**)&QKV, g_QKV);
    cudaGetSymbolAddress((void**)&S2,  g_S2);

    __nv_bfloat16 *Ah, *Al, *Xh, *Xl, *AOh, *AOl, *Yh, *Yl, *Fh, *Fl;
    __nv_bfloat16 *Wmh, *Wml, *Wqh, *Wql, *Wph, *Wpl, *W1h, *W1l, *W2h, *W2l, *Wch, *Wcl;
    cudaGetSymbolAddress((void**)&Ah,  gA_hi);   cudaGetSymbolAddress((void**)&Al,  gA_lo);
    cudaGetSymbolAddress((void**)&Xh,  gX_hi);   cudaGetSymbolAddress((void**)&Xl,  gX_lo);
    cudaGetSymbolAddress((void**)&AOh, gAO_hi);  cudaGetSymbolAddress((void**)&AOl, gAO_lo);
    cudaGetSymbolAddress((void**)&Yh,  gY_hi);   cudaGetSymbolAddress((void**)&Yl,  gY_lo);
    cudaGetSymbolAddress((void**)&Fh,  gF_hi);   cudaGetSymbolAddress((void**)&Fl,  gF_lo);
    cudaGetSymbolAddress((void**)&Wmh, gWmlp_hi);  cudaGetSymbolAddress((void**)&Wml, gWmlp_lo);
    cudaGetSymbolAddress((void**)&Wqh, gWqkv_hi);  cudaGetSymbolAddress((void**)&Wql, gWqkv_lo);
    cudaGetSymbolAddress((void**)&Wph, gWproj_hi); cudaGetSymbolAddress((void**)&Wpl, gWproj_lo);
    cudaGetSymbolAddress((void**)&W1h, gW1_hi);    cudaGetSymbolAddress((void**)&W1l, gW1_lo);
    cudaGetSymbolAddress((void**)&W2h, gW2_hi);    cudaGetSymbolAddress((void**)&W2l, gW2_lo);
    cudaGetSymbolAddress((void**)&Wch, gWc_hi);    cudaGetSymbolAddress((void**)&Wcl, gWc_lo);

    cudaFuncSetAttribute(attn_kernel, cudaFuncAttributeMaxDynamicSharedMemorySize,
                         ATT_SMEM_BYTES);
    cudaFuncSetAttribute(gemm_mma, cudaFuncAttributeMaxDynamicSharedMemorySize,
                         GSM_TOTAL);

    // App launch #4 = ncu capture target (conv GEMM).
    im2col2<<<dim3(4, 4, BA), 256>>>(buffer, Ah, Al);
    wsplit_mlp<<<(KIN * D_MOD + 255) / 256, 256>>>(W_mlp, Wmh, Wml);
    wsplit_kernel<<<(D_MOD * QKV_N + 255) / 256, 256>>>(Wqkv, D_MOD, QKV_N, Wqh, Wql);
    gemm_mma<<<dim3(D_MOD / 128, TOK_M / 128), 512, GSM_TOTAL>>>(
        Ah, Al, Wmh, Wml, T, TOK_M, D_MOD, KIN,
        nullptr, nullptr, 0, nullptr, nullptr, nullptr);
    im2col2<<<dim3(4, 4, BA), 256>>>(spa_pos, Ah, Al);
    gemm_mma<<<dim3(D_MOD / 128, TOK_M / 128), 512, GSM_TOTAL>>>(
        Ah, Al, Wmh, Wml, PE, TOK_M, D_MOD, KIN,
        nullptr, nullptr, 0, nullptr, nullptr, nullptr);
    wsplit_kernel<<<(D_MOD * D_MOD + 255) / 256, 256>>>(Wproj, D_MOD, D_MOD, Wph, Wpl);
    wsplit_kernel<<<(D_MOD * D_FF + 255) / 256, 256>>>(W1, D_MOD, D_FF, W1h, W1l);
    wsplit_kernel<<<(D_FF * D_MOD + 255) / 256, 256>>>(W2, D_FF, D_MOD, W2h, W2l);
    split_kernel<<<(CCH * D_MOD + 255) / 256, 256>>>(Wconv, (size_t)CCH * D_MOD, Wch, Wcl);

    ln_kernel<<<TOK_M, 256>>>(T, PE, g1, b1, Xh, Xl);

    gemm_mma<<<dim3(QKV_N / 128, TOK_M / 128), 512, GSM_TOTAL>>>(
        Xh, Xl, Wqh, Wql, QKV, TOK_M, QKV_N, D_MOD,
        nullptr, nullptr, 0, nullptr, nullptr, nullptr);

    attn_kernel<<<PIX, 256, ATT_SMEM_BYTES>>>(QKV, AOh, AOl, Wl, bl, Ww, bw, lamb);

    gemm_mma<<<dim3(D_MOD / 128, TOK_M / 128), 512, GSM_TOTAL>>>(
        AOh, AOl, Wph, Wpl, S2, TOK_M, D_MOD, D_MOD,
        bproj, T, 0, nullptr, nullptr, nullptr);

    ln_kernel<<<TOK_M, 256>>>(S2, nullptr, g2, b2, Yh, Yl);

    gemm_mma<<<dim3(D_FF / 128, TOK_M / 128), 512, GSM_TOTAL>>>(
        Yh, Yl, W1h, W1l, nullptr, TOK_M, D_FF, D_MOD,
        nullptr, nullptr, 1, Fh, Fl, nullptr);
    gemm_mma<<<dim3(D_MOD / 128, TOK_M / 128), 512, GSM_TOTAL>>>(
        Fh, Fl, W2h, W2l, nullptr, TOK_M, D_MOD, D_FF,
        nullptr, S2, 0, Xh, Xl, nullptr);

    gemm_mma<<<dim3(CCH / 128, TOK_M / 128), 512, GSM_TOTAL>>>(
        Xh, Xl, Wch, Wcl, nullptr, TOK_M, CCH, D_MOD,
        nullptr, nullptr, 0, nullptr, nullptr, out);
}